// round 1
// baseline (speedup 1.0000x reference)
#include <cuda_runtime.h>
#include <math.h>

// ---------------- problem constants ----------------
constexpr int NN = 20000;
constexpr int EE = 320000;
constexpr int FF = 128;   // F
constexpr int RB = 20;    // NRBF
constexpr float PI_F = 3.14159265358979323846f;
constexpr float EPS3 = 3e-15f;  // vnorm adds EPS per component, 3 components

// ---------------- device scratch (allowed: __device__ globals) ----------------
__device__ float g_rbf [(size_t)EE * RB];
__device__ float g_env [EE];
__device__ float g_unit[(size_t)EE * 3];
__device__ float g_eij [(size_t)EE * 128];
__device__ float g_ehid[(size_t)EE * 256];
__device__ float g_s   [(size_t)NN * 128];
__device__ float g_v0  [(size_t)NN * 384];
__device__ float g_v1  [(size_t)NN * 384];
__device__ float g_phi [(size_t)NN * 384];
__device__ float g_h1  [(size_t)NN * 128];
__device__ float g_uv  [(size_t)NN * 384];
__device__ float g_dot [(size_t)NN * 128];
__device__ float g_stk [(size_t)NN * 256];
__device__ float g_spl [(size_t)NN * 384];

__device__ __forceinline__ float swish(float x) {
    return x / (1.f + expf(-x));
}

// ---------------- init: s = embed[z], v0 = 0, out = 0 ----------------
__global__ void init_kernel(const float* __restrict__ emb, const int* __restrict__ z,
                            float* __restrict__ out) {
    int stride = gridDim.x * blockDim.x;
    for (int i = blockIdx.x * blockDim.x + threadIdx.x; i < NN * 384; i += stride) {
        g_v0[i] = 0.f;
        if (i < NN * 128) {
            int n = i >> 7, f = i & 127;
            g_s[i] = emb[z[n] * 128 + f];
        }
        if (i < NN * 3) out[i] = 0.f;
    }
}

// ---------------- per-edge geometry: dist, unit, env, rbf ----------------
__global__ void prep_kernel(const float* __restrict__ xyz, const int* __restrict__ nbrs) {
    int e = blockIdx.x * blockDim.x + threadIdx.x;
    if (e >= EE) return;
    int s = nbrs[2 * e], d = nbrs[2 * e + 1];
    float dx = xyz[d * 3 + 0] - xyz[s * 3 + 0];
    float dy = xyz[d * 3 + 1] - xyz[s * 3 + 1];
    float dz = xyz[d * 3 + 2] - xyz[s * 3 + 2];
    float d2 = dx * dx + dy * dy + dz * dz + EPS3;
    float dist = sqrtf(d2);
    float inv = 1.f / dist;
    g_unit[(size_t)e * 3 + 0] = dx * inv;
    g_unit[(size_t)e * 3 + 1] = dy * inv;
    g_unit[(size_t)e * 3 + 2] = dz * inv;
    float env = (dist < 5.f) ? 0.5f * (cosf(dist * (PI_F / 5.f)) + 1.f) : 0.f;
    g_env[e] = env;
    float base = dist * (PI_F / 5.f);
    #pragma unroll
    for (int k = 1; k <= RB; k++) {
        g_rbf[(size_t)e * RB + (k - 1)] = sinf(base * (float)k) * inv;
    }
}

// ---------------- generic tiled GEMM: C = [op](A @ W + b) ----------------
// A: M x K (row-major), W: K x NC, bias: NC.  One thread per output column.
// PAIR:  A row m is  s[src[m]] + s[dst[m]]   (gathered pair features)
// ENV:   multiply (acc+bias) by env[m] before store
// SWISH: apply swish
// ACCUM: C += instead of C =
template<int K, int NC, bool SWISH_F, bool ACCUM, bool PAIR, bool ENVF>
__global__ void __launch_bounds__(NC)
mlp_gemm(const float* __restrict__ A, const float* __restrict__ W,
         const float* __restrict__ bias, float* __restrict__ C,
         const int* __restrict__ nbrs, const float* __restrict__ env, int M) {
    constexpr int TM = 32;
    constexpr int PAD = 36;  // 36*4B = 144B rows: float4-aligned, mild bank spread
    __shared__ __align__(16) float As[K * PAD];

    int m0 = blockIdx.x * TM;
    int tid = threadIdx.x;

    for (int i = tid; i < TM * K; i += NC) {
        int r = i / K, c = i - r * K;
        int m = m0 + r;
        float val = 0.f;
        if (m < M) {
            if (PAIR) {
                int s = nbrs[2 * m], d = nbrs[2 * m + 1];
                val = A[(size_t)s * K + c] + A[(size_t)d * K + c];
            } else {
                val = A[(size_t)m * K + c];
            }
        }
        As[c * PAD + r] = val;
    }
    __syncthreads();

    float acc[TM];
    #pragma unroll
    for (int r = 0; r < TM; r++) acc[r] = 0.f;

    const float* Wj = W + tid;
    #pragma unroll 4
    for (int k = 0; k < K; k++) {
        float w = Wj[k * NC];
        const float4* row = reinterpret_cast<const float4*>(&As[k * PAD]);
        #pragma unroll
        for (int r4 = 0; r4 < TM / 4; r4++) {
            float4 a = row[r4];
            acc[r4 * 4 + 0] = fmaf(a.x, w, acc[r4 * 4 + 0]);
            acc[r4 * 4 + 1] = fmaf(a.y, w, acc[r4 * 4 + 1]);
            acc[r4 * 4 + 2] = fmaf(a.z, w, acc[r4 * 4 + 2]);
            acc[r4 * 4 + 3] = fmaf(a.w, w, acc[r4 * 4 + 3]);
        }
    }

    float bj = bias[tid];
    #pragma unroll
    for (int r = 0; r < TM; r++) {
        int m = m0 + r;
        if (m >= M) break;
        float v = acc[r] + bj;
        if (ENVF)    v *= env[m];
        if (SWISH_F) v = swish(v);
        size_t o = (size_t)m * NC + tid;
        if (ACCUM) C[o] += v; else C[o] = v;
    }
}

// ---------------- double-buffer copy for v ----------------
__global__ void copy_v(int sel) {
    const float4* a = reinterpret_cast<const float4*>(sel ? g_v1 : g_v0);
    float4* b = reinterpret_cast<float4*>(sel ? g_v0 : g_v1);
    int n4 = NN * 384 / 4;
    int i = blockIdx.x * blockDim.x + threadIdx.x;
    if (i < n4) b[i] = a[i];
}

// ---------------- fused message kernel ----------------
// w_s = (rbf @ dw + db) * env computed inline (weight columns in registers);
// inv = phi[dst] * w_s;  scatter split1 -> s[src],  dv -> v_new[src].
constexpr int TE = 32;
__global__ void __launch_bounds__(128)
msg_kernel(const int* __restrict__ nbrs, const float* __restrict__ dw,
           const float* __restrict__ db, int sel) {
    __shared__ float rbf_s[TE * RB];
    __shared__ float env_s[TE];
    __shared__ float unit_s[TE * 3];
    __shared__ int src_s[TE], dst_s[TE];

    int t = threadIdx.x;
    float dwr0[RB], dwr1[RB], dwr2[RB];
    #pragma unroll
    for (int k = 0; k < RB; k++) {
        dwr0[k] = dw[k * 384 + t];
        dwr1[k] = dw[k * 384 + t + 128];
        dwr2[k] = dw[k * 384 + t + 256];
    }
    float db0 = db[t], db1 = db[t + 128], db2 = db[t + 256];

    int e0 = blockIdx.x * TE;
    for (int i = t; i < TE * RB; i += 128) {
        int gi = e0 * RB + i;
        rbf_s[i] = (gi < EE * RB) ? g_rbf[gi] : 0.f;
    }
    if (t < TE) {
        int eg = e0 + t;
        if (eg < EE) {
            env_s[t] = g_env[eg];
            src_s[t] = nbrs[2 * eg];
            dst_s[t] = nbrs[2 * eg + 1];
            unit_s[t * 3 + 0] = g_unit[(size_t)eg * 3 + 0];
            unit_s[t * 3 + 1] = g_unit[(size_t)eg * 3 + 1];
            unit_s[t * 3 + 2] = g_unit[(size_t)eg * 3 + 2];
        }
    }
    __syncthreads();

    const float* vold = sel ? g_v1 : g_v0;
    float*       vnew = sel ? g_v0 : g_v1;
    int emax = min(TE, EE - e0);

    for (int e = 0; e < emax; e++) {
        float a0 = db0, a1 = db1, a2 = db2;
        #pragma unroll
        for (int k = 0; k < RB; k++) {
            float r = rbf_s[e * RB + k];
            a0 = fmaf(r, dwr0[k], a0);
            a1 = fmaf(r, dwr1[k], a1);
            a2 = fmaf(r, dwr2[k], a2);
        }
        float env = env_s[e];
        a0 *= env; a1 *= env; a2 *= env;

        int src = src_s[e], dst = dst_s[e];
        const float* ph = g_phi + (size_t)dst * 384;
        float s0 = ph[t] * a0;
        float s1 = ph[t + 128] * a1;
        float s2 = ph[t + 256] * a2;

        atomicAdd(&g_s[(size_t)src * 128 + t], s1);

        const float* vo = vold + (size_t)dst * 384 + 3 * t;
        float*       vn = vnew + (size_t)src * 384 + 3 * t;
        float ux = unit_s[e * 3], uy = unit_s[e * 3 + 1], uz = unit_s[e * 3 + 2];
        atomicAdd(&vn[0], fmaf(s0, vo[0], s2 * ux));
        atomicAdd(&vn[1], fmaf(s0, vo[1], s2 * uy));
        atomicAdd(&vn[2], fmaf(s0, vo[2], s2 * uz));
    }
}

// ---------------- update stage 1: u_v, v_v, |v_v|, dot(u_v,v_v), stack ----------------
constexpr int TA = 8;
__global__ void __launch_bounds__(128)
upd1_kernel(const float* __restrict__ U, const float* __restrict__ Vw, int sel) {
    __shared__ float v_s[TA * 384];
    int t = threadIdx.x;
    int n0 = blockIdx.x * TA;
    const float* vcur = sel ? g_v1 : g_v0;

    for (int i = t; i < TA * 384; i += 128) {
        size_t gi = (size_t)n0 * 384 + i;
        v_s[i] = (gi < (size_t)NN * 384) ? vcur[gi] : 0.f;
    }
    __syncthreads();

    float uv[TA][3], vv[TA][3];
    #pragma unroll
    for (int a = 0; a < TA; a++)
        #pragma unroll
        for (int d = 0; d < 3; d++) { uv[a][d] = 0.f; vv[a][d] = 0.f; }

    for (int f = 0; f < 128; f++) {
        float u = U[f * 128 + t];
        float w = Vw[f * 128 + t];
        #pragma unroll
        for (int a = 0; a < TA; a++) {
            float vx = v_s[a * 384 + f * 3 + 0];
            float vy = v_s[a * 384 + f * 3 + 1];
            float vz = v_s[a * 384 + f * 3 + 2];
            uv[a][0] = fmaf(vx, u, uv[a][0]);
            uv[a][1] = fmaf(vy, u, uv[a][1]);
            uv[a][2] = fmaf(vz, u, uv[a][2]);
            vv[a][0] = fmaf(vx, w, vv[a][0]);
            vv[a][1] = fmaf(vy, w, vv[a][1]);
            vv[a][2] = fmaf(vz, w, vv[a][2]);
        }
    }

    #pragma unroll
    for (int a = 0; a < TA; a++) {
        int n = n0 + a;
        if (n >= NN) break;
        float dt = uv[a][0] * vv[a][0] + uv[a][1] * vv[a][1] + uv[a][2] * vv[a][2];
        float vn = sqrtf(vv[a][0] * vv[a][0] + vv[a][1] * vv[a][1] + vv[a][2] * vv[a][2] + EPS3);
        g_uv[(size_t)n * 384 + 3 * t + 0] = uv[a][0];
        g_uv[(size_t)n * 384 + 3 * t + 1] = uv[a][1];
        g_uv[(size_t)n * 384 + 3 * t + 2] = uv[a][2];
        g_dot[(size_t)n * 128 + t] = dt;
        g_stk[(size_t)n * 256 + t] = g_s[(size_t)n * 128 + t];
        g_stk[(size_t)n * 256 + 128 + t] = vn;
    }
}

// ---------------- update apply: v += uv*a_vv ; s += dot*a_sv + a_ss ----------------
__global__ void apply_kernel(int sel) {
    int i = blockIdx.x * blockDim.x + threadIdx.x;
    if (i >= NN * 128) return;
    int n = i >> 7, g = i & 127;
    float avv = g_spl[(size_t)n * 384 + g];
    float asv = g_spl[(size_t)n * 384 + 128 + g];
    float ass = g_spl[(size_t)n * 384 + 256 + g];
    float* v = (sel ? g_v1 : g_v0) + (size_t)n * 384 + 3 * g;
    const float* uv = g_uv + (size_t)n * 384 + 3 * g;
    v[0] += uv[0] * avv;
    v[1] += uv[1] * avv;
    v[2] += uv[2] * avv;
    g_s[i] += g_dot[i] * asv + ass;
}

// ---------------- readout final: scalar = hid . ro_w2 + b ; scatter forces ----------------
__global__ void __launch_bounds__(256)
readout_kernel(const float* __restrict__ w2, const float* __restrict__ b2,
               const int* __restrict__ nbrs, float* __restrict__ out) {
    int warp = threadIdx.x >> 5, lane = threadIdx.x & 31;
    int e = blockIdx.x * 8 + warp;
    if (e >= EE) return;
    const float* h = g_ehid + (size_t)e * 256;
    float acc = 0.f;
    #pragma unroll
    for (int q = 0; q < 8; q++) {
        int idx = lane + 32 * q;
        acc = fmaf(h[idx], w2[idx], acc);
    }
    #pragma unroll
    for (int o = 16; o; o >>= 1) acc += __shfl_down_sync(0xffffffff, acc, o);
    if (lane == 0) {
        float s = acc + b2[0];
        int src = nbrs[2 * e], dst = nbrs[2 * e + 1];
        float fx = s * g_unit[(size_t)e * 3 + 0];
        float fy = s * g_unit[(size_t)e * 3 + 1];
        float fz = s * g_unit[(size_t)e * 3 + 2];
        atomicAdd(&out[src * 3 + 0], fx);
        atomicAdd(&out[src * 3 + 1], fy);
        atomicAdd(&out[src * 3 + 2], fz);
        atomicAdd(&out[dst * 3 + 0], -fx);
        atomicAdd(&out[dst * 3 + 1], -fy);
        atomicAdd(&out[dst * 3 + 2], -fz);
    }
}

// ---------------- host launcher ----------------
extern "C" void kernel_launch(void* const* d_in, const int* in_sizes, int n_in,
                              void* d_out, int out_size) {
    const float* xyz     = (const float*)d_in[0];
    const int*   z       = (const int*)  d_in[1];
    const int*   nbrs    = (const int*)  d_in[2];
    const float* emb     = (const float*)d_in[3];
    const float* de_w    = (const float*)d_in[4];
    const float* de_b    = (const float*)d_in[5];
    const float* msg_w1  = (const float*)d_in[6];
    const float* msg_b1  = (const float*)d_in[7];
    const float* msg_w2  = (const float*)d_in[8];
    const float* msg_b2  = (const float*)d_in[9];
    const float* msg_dw  = (const float*)d_in[10];
    const float* msg_db  = (const float*)d_in[11];
    const float* upd_u   = (const float*)d_in[12];
    const float* upd_v   = (const float*)d_in[13];
    const float* upd_w1  = (const float*)d_in[14];
    const float* upd_b1  = (const float*)d_in[15];
    const float* upd_w2  = (const float*)d_in[16];
    const float* upd_b2  = (const float*)d_in[17];
    const float* edge_w1 = (const float*)d_in[18];
    const float* edge_b1 = (const float*)d_in[19];
    const float* edge_w2 = (const float*)d_in[20];
    const float* edge_b2 = (const float*)d_in[21];
    const float* ro_w1   = (const float*)d_in[22];
    const float* ro_b1   = (const float*)d_in[23];
    const float* ro_w2   = (const float*)d_in[24];
    const float* ro_b2   = (const float*)d_in[25];
    float* out = (float*)d_out;

    float *p_rbf, *p_env, *p_eij, *p_ehid, *p_s, *p_phi, *p_h1, *p_stk, *p_spl;
    cudaGetSymbolAddress((void**)&p_rbf,  g_rbf);
    cudaGetSymbolAddress((void**)&p_env,  g_env);
    cudaGetSymbolAddress((void**)&p_eij,  g_eij);
    cudaGetSymbolAddress((void**)&p_ehid, g_ehid);
    cudaGetSymbolAddress((void**)&p_s,    g_s);
    cudaGetSymbolAddress((void**)&p_phi,  g_phi);
    cudaGetSymbolAddress((void**)&p_h1,   g_h1);
    cudaGetSymbolAddress((void**)&p_stk,  g_stk);
    cudaGetSymbolAddress((void**)&p_spl,  g_spl);

    const int gN = (NN + 31) / 32;   // 625
    const int gE = (EE + 31) / 32;   // 10000

    init_kernel<<<2048, 256>>>(emb, z, out);
    prep_kernel<<<(EE + 255) / 256, 256>>>(xyz, nbrs);

    // e_ij = (rbf @ de_w + de_b) * env
    mlp_gemm<RB, 128, false, false, false, true><<<gE, 128>>>(
        p_rbf, de_w, de_b, p_eij, nullptr, p_env, EE);

    for (int l = 0; l < 3; l++) {
        int sel = l & 1;          // current v buffer before message
        int cur = sel ^ 1;        // current v buffer after message

        // phi = swish(s @ msg_w1 + b1) @ msg_w2 + b2
        mlp_gemm<128, 128, true, false, false, false><<<gN, 128>>>(
            p_s, msg_w1 + l * 128 * 128, msg_b1 + l * 128, p_h1, nullptr, nullptr, NN);
        mlp_gemm<128, 384, false, false, false, false><<<gN, 384>>>(
            p_h1, msg_w2 + l * 128 * 384, msg_b2 + l * 384, p_phi, nullptr, nullptr, NN);

        copy_v<<<(NN * 384 / 4 + 255) / 256, 256>>>(sel);
        msg_kernel<<<(EE + TE - 1) / TE, 128>>>(nbrs, msg_dw + l * RB * 384,
                                                msg_db + l * 384, sel);

        // update block
        upd1_kernel<<<(NN + TA - 1) / TA, 128>>>(upd_u + l * 128 * 128,
                                                 upd_v + l * 128 * 128, cur);
        mlp_gemm<256, 128, true, false, false, false><<<gN, 128>>>(
            p_stk, upd_w1 + l * 256 * 128, upd_b1 + l * 128, p_h1, nullptr, nullptr, NN);
        mlp_gemm<128, 384, false, false, false, false><<<gN, 384>>>(
            p_h1, upd_w2 + l * 128 * 384, upd_b2 + l * 384, p_spl, nullptr, nullptr, NN);
        apply_kernel<<<(NN * 128 + 255) / 256, 256>>>(cur);

        // edge MLP: e_ij += swish((s[src]+s[dst]) @ w1 + b1) @ w2 + b2
        mlp_gemm<128, 256, true, false, true, false><<<gE, 256>>>(
            p_s, edge_w1 + l * 128 * 256, edge_b1 + l * 256, p_ehid, nbrs, nullptr, EE);
        mlp_gemm<256, 128, false, true, false, false><<<gE, 128>>>(
            p_ehid, edge_w2 + l * 256 * 128, edge_b2 + l * 128, p_eij, nullptr, nullptr, EE);
    }

    // readout
    mlp_gemm<128, 256, true, false, false, false><<<gE, 256>>>(
        p_eij, ro_w1, ro_b1, p_ehid, nullptr, nullptr, EE);
    readout_kernel<<<(EE + 7) / 8, 256>>>(ro_w2, ro_b2, nbrs, out);

    (void)in_sizes; (void)n_in; (void)out_size;
}

// round 2
// speedup vs baseline: 1.3670x; 1.3670x over previous
#include <cuda_runtime.h>
#include <math.h>

// ---------------- problem constants ----------------
constexpr int NN = 20000;
constexpr int EE = 320000;
constexpr int RB = 20;    // NRBF
constexpr float PI_F = 3.14159265358979323846f;
constexpr float EPS3 = 3e-15f;

// ---------------- device scratch ----------------
__device__ float g_rbf [(size_t)EE * RB];
__device__ float g_env [EE];
__device__ float g_unit[(size_t)EE * 3];
__device__ float g_eij [(size_t)EE * 128];
__device__ float g_s   [(size_t)NN * 128];
__device__ float g_v0  [(size_t)NN * 384];
__device__ float g_v1  [(size_t)NN * 384];
__device__ float g_phi [(size_t)NN * 384];
__device__ float g_h1  [(size_t)NN * 128];
__device__ float g_uv  [(size_t)NN * 384];
__device__ float g_dot [(size_t)NN * 128];
__device__ float g_stk [(size_t)NN * 256];
__device__ float g_spl [(size_t)NN * 384];
__device__ float g_t   [(size_t)NN * 256];   // node-level edge-MLP layer-1 output

__device__ __forceinline__ float swish(float x) {
    return x / (1.f + expf(-x));
}

// ---------------- init ----------------
__global__ void init_kernel(const float* __restrict__ emb, const int* __restrict__ z,
                            float* __restrict__ out) {
    int stride = gridDim.x * blockDim.x;
    for (int i = blockIdx.x * blockDim.x + threadIdx.x; i < NN * 384; i += stride) {
        g_v0[i] = 0.f;
        if (i < NN * 128) {
            int n = i >> 7, f = i & 127;
            g_s[i] = emb[z[n] * 128 + f];
        }
        if (i < NN * 3) out[i] = 0.f;
    }
}

// ---------------- per-edge geometry ----------------
__global__ void prep_kernel(const float* __restrict__ xyz, const int* __restrict__ nbrs) {
    int e = blockIdx.x * blockDim.x + threadIdx.x;
    if (e >= EE) return;
    int s = nbrs[2 * e], d = nbrs[2 * e + 1];
    float dx = xyz[d * 3 + 0] - xyz[s * 3 + 0];
    float dy = xyz[d * 3 + 1] - xyz[s * 3 + 1];
    float dz = xyz[d * 3 + 2] - xyz[s * 3 + 2];
    float d2 = dx * dx + dy * dy + dz * dz + EPS3;
    float dist = sqrtf(d2);
    float inv = 1.f / dist;
    g_unit[(size_t)e * 3 + 0] = dx * inv;
    g_unit[(size_t)e * 3 + 1] = dy * inv;
    g_unit[(size_t)e * 3 + 2] = dz * inv;
    float env = (dist < 5.f) ? 0.5f * (cosf(dist * (PI_F / 5.f)) + 1.f) : 0.f;
    g_env[e] = env;
    float base = dist * (PI_F / 5.f);
    #pragma unroll
    for (int k = 1; k <= RB; k++) {
        g_rbf[(size_t)e * RB + (k - 1)] = sinf(base * (float)k) * inv;
    }
}

// ---------------- small-K GEMM (only for rbf K=20 init of e_ij) ----------------
template<int K, int NC>
__global__ void __launch_bounds__(NC)
mlp_gemm_small(const float* __restrict__ A, const float* __restrict__ W,
               const float* __restrict__ bias, float* __restrict__ C,
               const float* __restrict__ env, int M) {
    constexpr int TM = 32;
    constexpr int PAD = 36;
    __shared__ __align__(16) float As[K * PAD];
    int m0 = blockIdx.x * TM;
    int tid = threadIdx.x;
    for (int i = tid; i < TM * K; i += NC) {
        int r = i / K, c = i - r * K;
        int m = m0 + r;
        As[c * PAD + r] = (m < M) ? A[(size_t)m * K + c] : 0.f;
    }
    __syncthreads();
    float acc[TM];
    #pragma unroll
    for (int r = 0; r < TM; r++) acc[r] = 0.f;
    const float* Wj = W + tid;
    #pragma unroll
    for (int k = 0; k < K; k++) {
        float w = Wj[k * NC];
        const float4* row = reinterpret_cast<const float4*>(&As[k * PAD]);
        #pragma unroll
        for (int r4 = 0; r4 < TM / 4; r4++) {
            float4 a = row[r4];
            acc[r4 * 4 + 0] = fmaf(a.x, w, acc[r4 * 4 + 0]);
            acc[r4 * 4 + 1] = fmaf(a.y, w, acc[r4 * 4 + 1]);
            acc[r4 * 4 + 2] = fmaf(a.z, w, acc[r4 * 4 + 2]);
            acc[r4 * 4 + 3] = fmaf(a.w, w, acc[r4 * 4 + 3]);
        }
    }
    float bj = bias[tid];
    #pragma unroll
    for (int r = 0; r < TM; r++) {
        int m = m0 + r;
        if (m >= M) break;
        C[(size_t)m * NC + tid] = (acc[r] + bj) * env[m];
    }
}

// ---------------- register-blocked GEMM: 64 rows x 128 cols per block ----------------
// 256 threads; each thread: 8 rows x 4 cols.
// PAIR_SWISH: A row m is swish(A[src[m]] + A[dst[m]]) (gathered)
// grid.y selects a 128-col slab; ldw = total output columns (= W row stride).
constexpr int GPAD = 72;  // padded row length of As (floats), 16B-aligned
template<int K, bool PAIR_SWISH, bool SWISH_OUT, bool ACCUM>
__global__ void __launch_bounds__(256)
gemm_rt(const float* __restrict__ A, const float* __restrict__ W, int ldw,
        const float* __restrict__ bias, float bias_scale, float* __restrict__ C,
        const int* __restrict__ nbrs, int M) {
    extern __shared__ __align__(16) float As[];  // [K][GPAD]
    int m0 = blockIdx.x * 64;
    int col0 = blockIdx.y * 128;
    int tid = threadIdx.x;

    constexpr int QK = K / 4;
    for (int q = tid; q < 64 * QK; q += 256) {
        int r = q / QK, c4 = (q - r * QK) * 4;
        int m = m0 + r;
        float4 v = make_float4(0.f, 0.f, 0.f, 0.f);
        if (m < M) {
            if (PAIR_SWISH) {
                int s = nbrs[2 * m], d = nbrs[2 * m + 1];
                float4 a = *(const float4*)&A[(size_t)s * K + c4];
                float4 b = *(const float4*)&A[(size_t)d * K + c4];
                v.x = swish(a.x + b.x);
                v.y = swish(a.y + b.y);
                v.z = swish(a.z + b.z);
                v.w = swish(a.w + b.w);
            } else {
                v = *(const float4*)&A[(size_t)m * K + c4];
            }
        }
        As[(c4 + 0) * GPAD + r] = v.x;
        As[(c4 + 1) * GPAD + r] = v.y;
        As[(c4 + 2) * GPAD + r] = v.z;
        As[(c4 + 3) * GPAD + r] = v.w;
    }
    __syncthreads();

    int ty = tid >> 5;   // 0..7 : rows ty*8 .. ty*8+7
    int tx = tid & 31;   // cols col0 + tx*4 .. +3
    float acc[8][4];
    #pragma unroll
    for (int r = 0; r < 8; r++)
        #pragma unroll
        for (int j = 0; j < 4; j++) acc[r][j] = 0.f;

    const float* Wp = W + col0 + tx * 4;
    #pragma unroll 4
    for (int k = 0; k < K; k++) {
        float4 w = *(const float4*)&Wp[(size_t)k * ldw];
        const float4* arow = reinterpret_cast<const float4*>(&As[k * GPAD + ty * 8]);
        float4 a0 = arow[0];
        float4 a1 = arow[1];
        float av[8] = {a0.x, a0.y, a0.z, a0.w, a1.x, a1.y, a1.z, a1.w};
        #pragma unroll
        for (int r = 0; r < 8; r++) {
            acc[r][0] = fmaf(av[r], w.x, acc[r][0]);
            acc[r][1] = fmaf(av[r], w.y, acc[r][1]);
            acc[r][2] = fmaf(av[r], w.z, acc[r][2]);
            acc[r][3] = fmaf(av[r], w.w, acc[r][3]);
        }
    }

    float4 b4 = *(const float4*)&bias[col0 + tx * 4];
    b4.x *= bias_scale; b4.y *= bias_scale; b4.z *= bias_scale; b4.w *= bias_scale;
    #pragma unroll
    for (int r = 0; r < 8; r++) {
        int m = m0 + ty * 8 + r;
        if (m >= M) continue;
        float4 o;
        o.x = acc[r][0] + b4.x;
        o.y = acc[r][1] + b4.y;
        o.z = acc[r][2] + b4.z;
        o.w = acc[r][3] + b4.w;
        if (SWISH_OUT) {
            o.x = swish(o.x); o.y = swish(o.y); o.z = swish(o.z); o.w = swish(o.w);
        }
        float* cp = &C[(size_t)m * ldw + col0 + tx * 4];
        if (ACCUM) {
            float4 old = *(const float4*)cp;
            o.x += old.x; o.y += old.y; o.z += old.z; o.w += old.w;
        }
        *(float4*)cp = o;
    }
}

// ---------------- double-buffer copy for v ----------------
__global__ void copy_v(int sel) {
    const float4* a = reinterpret_cast<const float4*>(sel ? g_v1 : g_v0);
    float4* b = reinterpret_cast<float4*>(sel ? g_v0 : g_v1);
    int n4 = NN * 384 / 4;
    int i = blockIdx.x * blockDim.x + threadIdx.x;
    if (i < n4) b[i] = a[i];
}

// ---------------- fused message kernel ----------------
constexpr int TE = 32;
__global__ void __launch_bounds__(128)
msg_kernel(const int* __restrict__ nbrs, const float* __restrict__ dw,
           const float* __restrict__ db, int sel) {
    __shared__ float rbf_s[TE * RB];
    __shared__ float env_s[TE];
    __shared__ float unit_s[TE * 3];
    __shared__ int src_s[TE], dst_s[TE];

    int t = threadIdx.x;
    float dwr0[RB], dwr1[RB], dwr2[RB];
    #pragma unroll
    for (int k = 0; k < RB; k++) {
        dwr0[k] = dw[k * 384 + t];
        dwr1[k] = dw[k * 384 + t + 128];
        dwr2[k] = dw[k * 384 + t + 256];
    }
    float db0 = db[t], db1 = db[t + 128], db2 = db[t + 256];

    int e0 = blockIdx.x * TE;
    for (int i = t; i < TE * RB; i += 128) {
        int gi = e0 * RB + i;
        rbf_s[i] = (gi < EE * RB) ? g_rbf[gi] : 0.f;
    }
    if (t < TE) {
        int eg = e0 + t;
        if (eg < EE) {
            env_s[t] = g_env[eg];
            src_s[t] = nbrs[2 * eg];
            dst_s[t] = nbrs[2 * eg + 1];
            unit_s[t * 3 + 0] = g_unit[(size_t)eg * 3 + 0];
            unit_s[t * 3 + 1] = g_unit[(size_t)eg * 3 + 1];
            unit_s[t * 3 + 2] = g_unit[(size_t)eg * 3 + 2];
        }
    }
    __syncthreads();

    const float* vold = sel ? g_v1 : g_v0;
    float*       vnew = sel ? g_v0 : g_v1;
    int emax = min(TE, EE - e0);

    for (int e = 0; e < emax; e++) {
        float a0 = db0, a1 = db1, a2 = db2;
        #pragma unroll
        for (int k = 0; k < RB; k++) {
            float r = rbf_s[e * RB + k];
            a0 = fmaf(r, dwr0[k], a0);
            a1 = fmaf(r, dwr1[k], a1);
            a2 = fmaf(r, dwr2[k], a2);
        }
        float env = env_s[e];
        a0 *= env; a1 *= env; a2 *= env;

        int src = src_s[e], dst = dst_s[e];
        const float* ph = g_phi + (size_t)dst * 384;
        float s0 = ph[t] * a0;
        float s1 = ph[t + 128] * a1;
        float s2 = ph[t + 256] * a2;

        atomicAdd(&g_s[(size_t)src * 128 + t], s1);

        const float* vo = vold + (size_t)dst * 384 + 3 * t;
        float*       vn = vnew + (size_t)src * 384 + 3 * t;
        float ux = unit_s[e * 3], uy = unit_s[e * 3 + 1], uz = unit_s[e * 3 + 2];
        atomicAdd(&vn[0], fmaf(s0, vo[0], s2 * ux));
        atomicAdd(&vn[1], fmaf(s0, vo[1], s2 * uy));
        atomicAdd(&vn[2], fmaf(s0, vo[2], s2 * uz));
    }
}

// ---------------- update stage 1 (float4 LDS) ----------------
constexpr int TA = 8;
__global__ void __launch_bounds__(128)
upd1_kernel(const float* __restrict__ U, const float* __restrict__ Vw, int sel) {
    __shared__ __align__(16) float v_s[TA * 384];
    int t = threadIdx.x;
    int n0 = blockIdx.x * TA;
    const float* vcur = sel ? g_v1 : g_v0;

    for (int i = t; i < TA * 384; i += 128) {
        size_t gi = (size_t)n0 * 384 + i;
        v_s[i] = (gi < (size_t)NN * 384) ? vcur[gi] : 0.f;
    }
    __syncthreads();

    float uv[TA][3], vv[TA][3];
    #pragma unroll
    for (int a = 0; a < TA; a++)
        #pragma unroll
        for (int d = 0; d < 3; d++) { uv[a][d] = 0.f; vv[a][d] = 0.f; }

    for (int f4 = 0; f4 < 32; f4++) {
        float u0 = U[(f4 * 4 + 0) * 128 + t];
        float u1 = U[(f4 * 4 + 1) * 128 + t];
        float u2 = U[(f4 * 4 + 2) * 128 + t];
        float u3 = U[(f4 * 4 + 3) * 128 + t];
        float w0 = Vw[(f4 * 4 + 0) * 128 + t];
        float w1 = Vw[(f4 * 4 + 1) * 128 + t];
        float w2 = Vw[(f4 * 4 + 2) * 128 + t];
        float w3 = Vw[(f4 * 4 + 3) * 128 + t];
        #pragma unroll
        for (int a = 0; a < TA; a++) {
            const float4* vp = reinterpret_cast<const float4*>(&v_s[a * 384 + f4 * 12]);
            float4 p0 = vp[0], p1 = vp[1], p2 = vp[2];
            // f4*4+0: (p0.x p0.y p0.z) ; +1: (p0.w p1.x p1.y) ; +2: (p1.z p1.w p2.x) ; +3: (p2.y p2.z p2.w)
            uv[a][0] = fmaf(p0.x, u0, fmaf(p0.w, u1, fmaf(p1.z, u2, fmaf(p2.y, u3, uv[a][0]))));
            uv[a][1] = fmaf(p0.y, u0, fmaf(p1.x, u1, fmaf(p1.w, u2, fmaf(p2.z, u3, uv[a][1]))));
            uv[a][2] = fmaf(p0.z, u0, fmaf(p1.y, u1, fmaf(p2.x, u2, fmaf(p2.w, u3, uv[a][2]))));
            vv[a][0] = fmaf(p0.x, w0, fmaf(p0.w, w1, fmaf(p1.z, w2, fmaf(p2.y, w3, vv[a][0]))));
            vv[a][1] = fmaf(p0.y, w0, fmaf(p1.x, w1, fmaf(p1.w, w2, fmaf(p2.z, w3, vv[a][1]))));
            vv[a][2] = fmaf(p0.z, w0, fmaf(p1.y, w1, fmaf(p2.x, w2, fmaf(p2.w, w3, vv[a][2]))));
        }
    }

    #pragma unroll
    for (int a = 0; a < TA; a++) {
        int n = n0 + a;
        if (n >= NN) break;
        float dt = uv[a][0] * vv[a][0] + uv[a][1] * vv[a][1] + uv[a][2] * vv[a][2];
        float vn = sqrtf(vv[a][0] * vv[a][0] + vv[a][1] * vv[a][1] + vv[a][2] * vv[a][2] + EPS3);
        g_uv[(size_t)n * 384 + 3 * t + 0] = uv[a][0];
        g_uv[(size_t)n * 384 + 3 * t + 1] = uv[a][1];
        g_uv[(size_t)n * 384 + 3 * t + 2] = uv[a][2];
        g_dot[(size_t)n * 128 + t] = dt;
        g_stk[(size_t)n * 256 + t] = g_s[(size_t)n * 128 + t];
        g_stk[(size_t)n * 256 + 128 + t] = vn;
    }
}

// ---------------- update apply ----------------
__global__ void apply_kernel(int sel) {
    int i = blockIdx.x * blockDim.x + threadIdx.x;
    if (i >= NN * 128) return;
    int n = i >> 7, g = i & 127;
    float avv = g_spl[(size_t)n * 384 + g];
    float asv = g_spl[(size_t)n * 384 + 128 + g];
    float ass = g_spl[(size_t)n * 384 + 256 + g];
    float* v = (sel ? g_v1 : g_v0) + (size_t)n * 384 + 3 * g;
    const float* uv = g_uv + (size_t)n * 384 + 3 * g;
    v[0] += uv[0] * avv;
    v[1] += uv[1] * avv;
    v[2] += uv[2] * avv;
    g_s[i] += g_dot[i] * asv + ass;
}

// ---------------- fused readout: swish(e_ij@W1+b1)@w2 + b2 -> forces ----------------
// 64 edges per block, 512 threads (8 row-groups x 64 col-threads x 4 cols).
__global__ void __launch_bounds__(512)
readout_fused(const float* __restrict__ W1, const float* __restrict__ b1,
              const float* __restrict__ w2, const float* __restrict__ b2,
              const int* __restrict__ nbrs, float* __restrict__ out) {
    __shared__ __align__(16) float As[128 * GPAD];
    __shared__ float red[64][2];
    int m0 = blockIdx.x * 64;
    int tid = threadIdx.x;

    for (int q = tid; q < 64 * 32; q += 512) {
        int r = q / 32, c4 = (q & 31) * 4;
        int m = m0 + r;
        float4 v = make_float4(0.f, 0.f, 0.f, 0.f);
        if (m < EE) v = *(const float4*)&g_eij[(size_t)m * 128 + c4];
        As[(c4 + 0) * GPAD + r] = v.x;
        As[(c4 + 1) * GPAD + r] = v.y;
        As[(c4 + 2) * GPAD + r] = v.z;
        As[(c4 + 3) * GPAD + r] = v.w;
    }
    __syncthreads();

    int tyr = tid >> 6;       // 0..7 : rows tyr*8..+7
    int txc = tid & 63;       // cols txc*4..+3 of 256
    float acc[8][4];
    #pragma unroll
    for (int r = 0; r < 8; r++)
        #pragma unroll
        for (int j = 0; j < 4; j++) acc[r][j] = 0.f;

    const float* Wp = W1 + txc * 4;
    #pragma unroll 4
    for (int k = 0; k < 128; k++) {
        float4 w = *(const float4*)&Wp[(size_t)k * 256];
        const float4* arow = reinterpret_cast<const float4*>(&As[k * GPAD + tyr * 8]);
        float4 a0 = arow[0];
        float4 a1 = arow[1];
        float av[8] = {a0.x, a0.y, a0.z, a0.w, a1.x, a1.y, a1.z, a1.w};
        #pragma unroll
        for (int r = 0; r < 8; r++) {
            acc[r][0] = fmaf(av[r], w.x, acc[r][0]);
            acc[r][1] = fmaf(av[r], w.y, acc[r][1]);
            acc[r][2] = fmaf(av[r], w.z, acc[r][2]);
            acc[r][3] = fmaf(av[r], w.w, acc[r][3]);
        }
    }

    float4 bb = *(const float4*)&b1[txc * 4];
    float4 ww = *(const float4*)&w2[txc * 4];
    float part[8];
    #pragma unroll
    for (int r = 0; r < 8; r++) {
        part[r] = swish(acc[r][0] + bb.x) * ww.x
                + swish(acc[r][1] + bb.y) * ww.y
                + swish(acc[r][2] + bb.z) * ww.z
                + swish(acc[r][3] + bb.w) * ww.w;
    }
    #pragma unroll
    for (int r = 0; r < 8; r++) {
        #pragma unroll
        for (int o = 16; o; o >>= 1)
            part[r] += __shfl_xor_sync(0xffffffff, part[r], o);
    }
    int wh = (tid >> 5) & 1;  // which half of txc this warp covers
    if ((tid & 31) == 0) {
        #pragma unroll
        for (int r = 0; r < 8; r++) red[tyr * 8 + r][wh] = part[r];
    }
    __syncthreads();

    if (tid < 64) {
        int e = m0 + tid;
        if (e < EE) {
            float s = red[tid][0] + red[tid][1] + b2[0];
            int src = nbrs[2 * e], dst = nbrs[2 * e + 1];
            float fx = s * g_unit[(size_t)e * 3 + 0];
            float fy = s * g_unit[(size_t)e * 3 + 1];
            float fz = s * g_unit[(size_t)e * 3 + 2];
            atomicAdd(&out[src * 3 + 0], fx);
            atomicAdd(&out[src * 3 + 1], fy);
            atomicAdd(&out[src * 3 + 2], fz);
            atomicAdd(&out[dst * 3 + 0], -fx);
            atomicAdd(&out[dst * 3 + 1], -fy);
            atomicAdd(&out[dst * 3 + 2], -fz);
        }
    }
}

// ---------------- host launcher ----------------
extern "C" void kernel_launch(void* const* d_in, const int* in_sizes, int n_in,
                              void* d_out, int out_size) {
    const float* xyz     = (const float*)d_in[0];
    const int*   z       = (const int*)  d_in[1];
    const int*   nbrs    = (const int*)  d_in[2];
    const float* emb     = (const float*)d_in[3];
    const float* de_w    = (const float*)d_in[4];
    const float* de_b    = (const float*)d_in[5];
    const float* msg_w1  = (const float*)d_in[6];
    const float* msg_b1  = (const float*)d_in[7];
    const float* msg_w2  = (const float*)d_in[8];
    const float* msg_b2  = (const float*)d_in[9];
    const float* msg_dw  = (const float*)d_in[10];
    const float* msg_db  = (const float*)d_in[11];
    const float* upd_u   = (const float*)d_in[12];
    const float* upd_v   = (const float*)d_in[13];
    const float* upd_w1  = (const float*)d_in[14];
    const float* upd_b1  = (const float*)d_in[15];
    const float* upd_w2  = (const float*)d_in[16];
    const float* upd_b2  = (const float*)d_in[17];
    const float* edge_w1 = (const float*)d_in[18];
    const float* edge_b1 = (const float*)d_in[19];
    const float* edge_w2 = (const float*)d_in[20];
    const float* edge_b2 = (const float*)d_in[21];
    const float* ro_w1   = (const float*)d_in[22];
    const float* ro_b1   = (const float*)d_in[23];
    const float* ro_w2   = (const float*)d_in[24];
    const float* ro_b2   = (const float*)d_in[25];
    float* out = (float*)d_out;

    float *p_rbf, *p_env, *p_eij, *p_s, *p_phi, *p_h1, *p_stk, *p_spl, *p_t;
    cudaGetSymbolAddress((void**)&p_rbf,  g_rbf);
    cudaGetSymbolAddress((void**)&p_env,  g_env);
    cudaGetSymbolAddress((void**)&p_eij,  g_eij);
    cudaGetSymbolAddress((void**)&p_s,    g_s);
    cudaGetSymbolAddress((void**)&p_phi,  g_phi);
    cudaGetSymbolAddress((void**)&p_h1,   g_h1);
    cudaGetSymbolAddress((void**)&p_stk,  g_stk);
    cudaGetSymbolAddress((void**)&p_spl,  g_spl);
    cudaGetSymbolAddress((void**)&p_t,    g_t);

    // raise dynamic smem cap for K=256 instantiations (73.7 KB)
    cudaFuncSetAttribute(gemm_rt<256, false, true,  false>,
                         cudaFuncAttributeMaxDynamicSharedMemorySize, 256 * GPAD * 4);
    cudaFuncSetAttribute(gemm_rt<256, true,  false, true>,
                         cudaFuncAttributeMaxDynamicSharedMemorySize, 256 * GPAD * 4);

    const int smem128 = 128 * GPAD * 4;
    const int smem256 = 256 * GPAD * 4;
    const int gN = (NN + 63) / 64;   // 313
    const int gE = (EE + 63) / 64;   // 5000

    init_kernel<<<2048, 256>>>(emb, z, out);
    prep_kernel<<<(EE + 255) / 256, 256>>>(xyz, nbrs);

    // e_ij = (rbf @ de_w + de_b) * env
    mlp_gemm_small<RB, 128><<<(EE + 31) / 32, 128>>>(p_rbf, de_w, de_b, p_eij, p_env, EE);

    for (int l = 0; l < 3; l++) {
        int sel = l & 1;
        int cur = sel ^ 1;

        // phi = swish(s @ msg_w1 + b1) @ msg_w2 + b2
        gemm_rt<128, false, true, false><<<dim3(gN, 1), 256, smem128>>>(
            p_s, msg_w1 + l * 128 * 128, 128, msg_b1 + l * 128, 1.f, p_h1, nullptr, NN);
        gemm_rt<128, false, false, false><<<dim3(gN, 3), 256, smem128>>>(
            p_h1, msg_w2 + l * 128 * 384, 384, msg_b2 + l * 384, 1.f, p_phi, nullptr, NN);

        copy_v<<<(NN * 384 / 4 + 255) / 256, 256>>>(sel);
        msg_kernel<<<(EE + TE - 1) / TE, 128>>>(nbrs, msg_dw + l * RB * 384,
                                                msg_db + l * 384, sel);

        // update block
        upd1_kernel<<<(NN + TA - 1) / TA, 128>>>(upd_u + l * 128 * 128,
                                                 upd_v + l * 128 * 128, cur);
        gemm_rt<256, false, true, false><<<dim3(gN, 1), 256, smem256>>>(
            p_stk, upd_w1 + l * 256 * 128, 128, upd_b1 + l * 128, 1.f, p_h1, nullptr, NN);
        gemm_rt<128, false, false, false><<<dim3(gN, 3), 256, smem128>>>(
            p_h1, upd_w2 + l * 128 * 384, 384, upd_b2 + l * 384, 1.f, p_spl, nullptr, NN);
        apply_kernel<<<(NN * 128 + 255) / 256, 256>>>(cur);

        // edge MLP, factored: t = s @ edge_w1 + 0.5*b1 per NODE;
        // then e_ij += swish(t[src]+t[dst]) @ edge_w2 + b2 per EDGE.
        gemm_rt<128, false, false, false><<<dim3(gN, 2), 256, smem128>>>(
            p_s, edge_w1 + l * 128 * 256, 256, edge_b1 + l * 256, 0.5f, p_t, nullptr, NN);
        gemm_rt<256, true, false, true><<<dim3(gE, 1), 256, smem256>>>(
            p_t, edge_w2 + l * 256 * 128, 128, edge_b2 + l * 128, 1.f, p_eij, nbrs, EE);
    }

    // fused readout
    readout_fused<<<gE, 512>>>(ro_w1, ro_b1, ro_w2, ro_b2, nbrs, out);

    (void)in_sizes; (void)n_in; (void)out_size;
}

// round 4
// speedup vs baseline: 1.6011x; 1.1713x over previous
#include <cuda_runtime.h>
#include <cuda_fp16.h>
#include <math.h>

// ---------------- problem constants ----------------
constexpr int NN = 20000;
constexpr int EE = 320000;
constexpr int RB = 20;    // NRBF
constexpr float PI_F = 3.14159265358979323846f;
constexpr float EPS3 = 3e-15f;

// ---------------- device scratch ----------------
__device__ float g_rbf [(size_t)EE * RB];
__device__ float g_env [EE];
__device__ float g_unit[(size_t)EE * 3];
__device__ float g_eij [(size_t)EE * 128];
__device__ float g_s   [(size_t)NN * 128];
__device__ float g_v0  [(size_t)NN * 384];
__device__ float g_v1  [(size_t)NN * 384];
__device__ float g_phi [(size_t)NN * 384];
__device__ float g_h1  [(size_t)NN * 128];
__device__ float g_uv  [(size_t)NN * 384];
__device__ float g_dot [(size_t)NN * 128];
__device__ float g_stk [(size_t)NN * 256];
__device__ float g_spl [(size_t)NN * 384];
__device__ float g_t   [(size_t)NN * 256];   // node-level edge-MLP layer-1 output

__device__ __forceinline__ float swish(float x) {
    return x / (1.f + expf(-x));
}

// fp16 two-term split: x ~= hi + lo, residual ~2^-22 relative
__device__ __forceinline__ void split_h(float x, __half& hi, __half& lo) {
    hi = __float2half_rn(x);
    lo = __float2half_rn(x - __half2float(hi));
}

// HMMA m16n8k16 fp16 -> fp32
__device__ __forceinline__ void hmma(float* d, const unsigned* a, const unsigned* b) {
    asm volatile(
        "mma.sync.aligned.m16n8k16.row.col.f32.f16.f16.f32 "
        "{%0,%1,%2,%3}, {%4,%5,%6,%7}, {%8,%9}, {%0,%1,%2,%3};"
        : "+f"(d[0]), "+f"(d[1]), "+f"(d[2]), "+f"(d[3])
        : "r"(a[0]), "r"(a[1]), "r"(a[2]), "r"(a[3]), "r"(b[0]), "r"(b[1]));
}

// ---------------- init ----------------
__global__ void init_kernel(const float* __restrict__ emb, const int* __restrict__ z,
                            float* __restrict__ out) {
    int stride = gridDim.x * blockDim.x;
    for (int i = blockIdx.x * blockDim.x + threadIdx.x; i < NN * 384; i += stride) {
        g_v0[i] = 0.f;
        if (i < NN * 128) {
            int n = i >> 7, f = i & 127;
            g_s[i] = emb[z[n] * 128 + f];
        }
        if (i < NN * 3) out[i] = 0.f;
    }
}

// ---------------- per-edge geometry ----------------
__global__ void prep_kernel(const float* __restrict__ xyz, const int* __restrict__ nbrs) {
    int e = blockIdx.x * blockDim.x + threadIdx.x;
    if (e >= EE) return;
    int s = nbrs[2 * e], d = nbrs[2 * e + 1];
    float dx = xyz[d * 3 + 0] - xyz[s * 3 + 0];
    float dy = xyz[d * 3 + 1] - xyz[s * 3 + 1];
    float dz = xyz[d * 3 + 2] - xyz[s * 3 + 2];
    float d2 = dx * dx + dy * dy + dz * dz + EPS3;
    float dist = sqrtf(d2);
    float inv = 1.f / dist;
    g_unit[(size_t)e * 3 + 0] = dx * inv;
    g_unit[(size_t)e * 3 + 1] = dy * inv;
    g_unit[(size_t)e * 3 + 2] = dz * inv;
    float env = (dist < 5.f) ? 0.5f * (cosf(dist * (PI_F / 5.f)) + 1.f) : 0.f;
    g_env[e] = env;
    float base = dist * (PI_F / 5.f);
    #pragma unroll
    for (int k = 1; k <= RB; k++) {
        g_rbf[(size_t)e * RB + (k - 1)] = sinf(base * (float)k) * inv;
    }
}

// ---------------- small-K GEMM (rbf K=20 init of e_ij) ----------------
template<int K, int NC>
__global__ void __launch_bounds__(NC)
mlp_gemm_small(const float* __restrict__ A, const float* __restrict__ W,
               const float* __restrict__ bias, float* __restrict__ C,
               const float* __restrict__ env, int M) {
    constexpr int TM = 32;
    constexpr int PAD = 36;
    __shared__ __align__(16) float As[K * PAD];
    int m0 = blockIdx.x * TM;
    int tid = threadIdx.x;
    for (int i = tid; i < TM * K; i += NC) {
        int r = i / K, c = i - r * K;
        int m = m0 + r;
        As[c * PAD + r] = (m < M) ? A[(size_t)m * K + c] : 0.f;
    }
    __syncthreads();
    float acc[TM];
    #pragma unroll
    for (int r = 0; r < TM; r++) acc[r] = 0.f;
    const float* Wj = W + tid;
    #pragma unroll
    for (int k = 0; k < K; k++) {
        float w = Wj[k * NC];
        const float4* row = reinterpret_cast<const float4*>(&As[k * PAD]);
        #pragma unroll
        for (int r4 = 0; r4 < TM / 4; r4++) {
            float4 a = row[r4];
            acc[r4 * 4 + 0] = fmaf(a.x, w, acc[r4 * 4 + 0]);
            acc[r4 * 4 + 1] = fmaf(a.y, w, acc[r4 * 4 + 1]);
            acc[r4 * 4 + 2] = fmaf(a.z, w, acc[r4 * 4 + 2]);
            acc[r4 * 4 + 3] = fmaf(a.w, w, acc[r4 * 4 + 3]);
        }
    }
    float bj = bias[tid];
    #pragma unroll
    for (int r = 0; r < TM; r++) {
        int m = m0 + r;
        if (m >= M) break;
        C[(size_t)m * NC + tid] = (acc[r] + bj) * env[m];
    }
}

// ---------------- register-blocked GEMM (node-level MLPs) ----------------
constexpr int GPAD = 72;
template<int K, bool SWISH_OUT>
__global__ void __launch_bounds__(256)
gemm_rt(const float* __restrict__ A, const float* __restrict__ W, int ldw,
        const float* __restrict__ bias, float bias_scale, float* __restrict__ C,
        int M) {
    extern __shared__ __align__(16) float As[];  // [K][GPAD]
    int m0 = blockIdx.x * 64;
    int col0 = blockIdx.y * 128;
    int tid = threadIdx.x;

    constexpr int QK = K / 4;
    for (int q = tid; q < 64 * QK; q += 256) {
        int r = q / QK, c4 = (q - r * QK) * 4;
        int m = m0 + r;
        float4 v = make_float4(0.f, 0.f, 0.f, 0.f);
        if (m < M) v = *(const float4*)&A[(size_t)m * K + c4];
        As[(c4 + 0) * GPAD + r] = v.x;
        As[(c4 + 1) * GPAD + r] = v.y;
        As[(c4 + 2) * GPAD + r] = v.z;
        As[(c4 + 3) * GPAD + r] = v.w;
    }
    __syncthreads();

    int ty = tid >> 5;
    int tx = tid & 31;
    float acc[8][4];
    #pragma unroll
    for (int r = 0; r < 8; r++)
        #pragma unroll
        for (int j = 0; j < 4; j++) acc[r][j] = 0.f;

    const float* Wp = W + col0 + tx * 4;
    #pragma unroll 4
    for (int k = 0; k < K; k++) {
        float4 w = *(const float4*)&Wp[(size_t)k * ldw];
        const float4* arow = reinterpret_cast<const float4*>(&As[k * GPAD + ty * 8]);
        float4 a0 = arow[0];
        float4 a1 = arow[1];
        float av[8] = {a0.x, a0.y, a0.z, a0.w, a1.x, a1.y, a1.z, a1.w};
        #pragma unroll
        for (int r = 0; r < 8; r++) {
            acc[r][0] = fmaf(av[r], w.x, acc[r][0]);
            acc[r][1] = fmaf(av[r], w.y, acc[r][1]);
            acc[r][2] = fmaf(av[r], w.z, acc[r][2]);
            acc[r][3] = fmaf(av[r], w.w, acc[r][3]);
        }
    }

    float4 b4 = *(const float4*)&bias[col0 + tx * 4];
    b4.x *= bias_scale; b4.y *= bias_scale; b4.z *= bias_scale; b4.w *= bias_scale;
    #pragma unroll
    for (int r = 0; r < 8; r++) {
        int m = m0 + ty * 8 + r;
        if (m >= M) continue;
        float4 o;
        o.x = acc[r][0] + b4.x;
        o.y = acc[r][1] + b4.y;
        o.z = acc[r][2] + b4.z;
        o.w = acc[r][3] + b4.w;
        if (SWISH_OUT) {
            o.x = swish(o.x); o.y = swish(o.y); o.z = swish(o.z); o.w = swish(o.w);
        }
        *(float4*)&C[(size_t)m * ldw + col0 + tx * 4] = o;
    }
}

// ---------------- double-buffer copy for v ----------------
__global__ void copy_v(int sel) {
    const float4* a = reinterpret_cast<const float4*>(sel ? g_v1 : g_v0);
    float4* b = reinterpret_cast<float4*>(sel ? g_v0 : g_v1);
    int n4 = NN * 384 / 4;
    int i = blockIdx.x * blockDim.x + threadIdx.x;
    if (i < n4) b[i] = a[i];
}

// ---------------- fused message kernel ----------------
constexpr int TE = 32;
__global__ void __launch_bounds__(128)
msg_kernel(const int* __restrict__ nbrs, const float* __restrict__ dw,
           const float* __restrict__ db, int sel) {
    __shared__ float rbf_s[TE * RB];
    __shared__ float env_s[TE];
    __shared__ float unit_s[TE * 3];
    __shared__ int src_s[TE], dst_s[TE];

    int t = threadIdx.x;
    float dwr0[RB], dwr1[RB], dwr2[RB];
    #pragma unroll
    for (int k = 0; k < RB; k++) {
        dwr0[k] = dw[k * 384 + t];
        dwr1[k] = dw[k * 384 + t + 128];
        dwr2[k] = dw[k * 384 + t + 256];
    }
    float db0 = db[t], db1 = db[t + 128], db2 = db[t + 256];

    int e0 = blockIdx.x * TE;
    for (int i = t; i < TE * RB; i += 128) {
        int gi = e0 * RB + i;
        rbf_s[i] = (gi < EE * RB) ? g_rbf[gi] : 0.f;
    }
    if (t < TE) {
        int eg = e0 + t;
        if (eg < EE) {
            env_s[t] = g_env[eg];
            src_s[t] = nbrs[2 * eg];
            dst_s[t] = nbrs[2 * eg + 1];
            unit_s[t * 3 + 0] = g_unit[(size_t)eg * 3 + 0];
            unit_s[t * 3 + 1] = g_unit[(size_t)eg * 3 + 1];
            unit_s[t * 3 + 2] = g_unit[(size_t)eg * 3 + 2];
        }
    }
    __syncthreads();

    const float* vold = sel ? g_v1 : g_v0;
    float*       vnew = sel ? g_v0 : g_v1;
    int emax = min(TE, EE - e0);

    for (int e = 0; e < emax; e++) {
        float a0 = db0, a1 = db1, a2 = db2;
        #pragma unroll
        for (int k = 0; k < RB; k++) {
            float r = rbf_s[e * RB + k];
            a0 = fmaf(r, dwr0[k], a0);
            a1 = fmaf(r, dwr1[k], a1);
            a2 = fmaf(r, dwr2[k], a2);
        }
        float env = env_s[e];
        a0 *= env; a1 *= env; a2 *= env;

        int src = src_s[e], dst = dst_s[e];
        const float* ph = g_phi + (size_t)dst * 384;
        float s0 = ph[t] * a0;
        float s1 = ph[t + 128] * a1;
        float s2 = ph[t + 256] * a2;

        atomicAdd(&g_s[(size_t)src * 128 + t], s1);

        const float* vo = vold + (size_t)dst * 384 + 3 * t;
        float*       vn = vnew + (size_t)src * 384 + 3 * t;
        float ux = unit_s[e * 3], uy = unit_s[e * 3 + 1], uz = unit_s[e * 3 + 2];
        atomicAdd(&vn[0], fmaf(s0, vo[0], s2 * ux));
        atomicAdd(&vn[1], fmaf(s0, vo[1], s2 * uy));
        atomicAdd(&vn[2], fmaf(s0, vo[2], s2 * uz));
    }
}

// ---------------- update stage 1 ----------------
constexpr int TA = 8;
__global__ void __launch_bounds__(128)
upd1_kernel(const float* __restrict__ U, const float* __restrict__ Vw, int sel) {
    __shared__ __align__(16) float v_s[TA * 384];
    int t = threadIdx.x;
    int n0 = blockIdx.x * TA;
    const float* vcur = sel ? g_v1 : g_v0;

    for (int i = t; i < TA * 384; i += 128) {
        size_t gi = (size_t)n0 * 384 + i;
        v_s[i] = (gi < (size_t)NN * 384) ? vcur[gi] : 0.f;
    }
    __syncthreads();

    float uv[TA][3], vv[TA][3];
    #pragma unroll
    for (int a = 0; a < TA; a++)
        #pragma unroll
        for (int d = 0; d < 3; d++) { uv[a][d] = 0.f; vv[a][d] = 0.f; }

    for (int f4 = 0; f4 < 32; f4++) {
        float u0 = U[(f4 * 4 + 0) * 128 + t];
        float u1 = U[(f4 * 4 + 1) * 128 + t];
        float u2 = U[(f4 * 4 + 2) * 128 + t];
        float u3 = U[(f4 * 4 + 3) * 128 + t];
        float w0 = Vw[(f4 * 4 + 0) * 128 + t];
        float w1 = Vw[(f4 * 4 + 1) * 128 + t];
        float w2 = Vw[(f4 * 4 + 2) * 128 + t];
        float w3 = Vw[(f4 * 4 + 3) * 128 + t];
        #pragma unroll
        for (int a = 0; a < TA; a++) {
            const float4* vp = reinterpret_cast<const float4*>(&v_s[a * 384 + f4 * 12]);
            float4 p0 = vp[0], p1 = vp[1], p2 = vp[2];
            uv[a][0] = fmaf(p0.x, u0, fmaf(p0.w, u1, fmaf(p1.z, u2, fmaf(p2.y, u3, uv[a][0]))));
            uv[a][1] = fmaf(p0.y, u0, fmaf(p1.x, u1, fmaf(p1.w, u2, fmaf(p2.z, u3, uv[a][1]))));
            uv[a][2] = fmaf(p0.z, u0, fmaf(p1.y, u1, fmaf(p2.x, u2, fmaf(p2.w, u3, uv[a][2]))));
            vv[a][0] = fmaf(p0.x, w0, fmaf(p0.w, w1, fmaf(p1.z, w2, fmaf(p2.y, w3, vv[a][0]))));
            vv[a][1] = fmaf(p0.y, w0, fmaf(p1.x, w1, fmaf(p1.w, w2, fmaf(p2.z, w3, vv[a][1]))));
            vv[a][2] = fmaf(p0.z, w0, fmaf(p1.y, w1, fmaf(p2.x, w2, fmaf(p2.w, w3, vv[a][2]))));
        }
    }

    #pragma unroll
    for (int a = 0; a < TA; a++) {
        int n = n0 + a;
        if (n >= NN) break;
        float dt = uv[a][0] * vv[a][0] + uv[a][1] * vv[a][1] + uv[a][2] * vv[a][2];
        float vn = sqrtf(vv[a][0] * vv[a][0] + vv[a][1] * vv[a][1] + vv[a][2] * vv[a][2] + EPS3);
        g_uv[(size_t)n * 384 + 3 * t + 0] = uv[a][0];
        g_uv[(size_t)n * 384 + 3 * t + 1] = uv[a][1];
        g_uv[(size_t)n * 384 + 3 * t + 2] = uv[a][2];
        g_dot[(size_t)n * 128 + t] = dt;
        g_stk[(size_t)n * 256 + t] = g_s[(size_t)n * 128 + t];
        g_stk[(size_t)n * 256 + 128 + t] = vn;
    }
}

// ---------------- update apply ----------------
__global__ void apply_kernel(int sel) {
    int i = blockIdx.x * blockDim.x + threadIdx.x;
    if (i >= NN * 128) return;
    int n = i >> 7, g = i & 127;
    float avv = g_spl[(size_t)n * 384 + g];
    float asv = g_spl[(size_t)n * 384 + 128 + g];
    float ass = g_spl[(size_t)n * 384 + 256 + g];
    float* v = (sel ? g_v1 : g_v0) + (size_t)n * 384 + 3 * g;
    const float* uv = g_uv + (size_t)n * 384 + 3 * g;
    v[0] += uv[0] * avv;
    v[1] += uv[1] * avv;
    v[2] += uv[2] * avv;
    g_s[i] += g_dot[i] * asv + ass;
}

// ================ HMMA edge layer-2 GEMM ================
// e_ij[128 edges,128] += swish(t[src]+t[dst])[128,256] @ W[256,128] + b
// fp16 split emulation (A0B0 + A0B1 + A1B0), fp32 accumulators.
// smem: A_hi/A_lo [128][72] halves, B_hi/B_lo [128 n][72 k] halves = 72KB.
constexpr int HP = 72;  // padded half stride (144B rows)
__global__ void __launch_bounds__(256)
edge2_mma(const float* __restrict__ t, const float* __restrict__ W,
          const float* __restrict__ bias, const int* __restrict__ nbrs,
          float* __restrict__ eij) {
    extern __shared__ __align__(16) __half hsm[];
    __half* Ah = hsm;
    __half* Al = Ah + 128 * HP;
    __half* Bh = Al + 128 * HP;
    __half* Bl = Bh + 128 * HP;
    __shared__ int s_src[128], s_dst[128];

    int tid = threadIdx.x;
    int wid = tid >> 5, lane = tid & 31;
    int g = lane >> 2, tq = lane & 3;
    int m0 = (wid & 3) * 32;
    int n0w = (wid >> 2) * 64;
    int e0 = blockIdx.x * 128;

    if (tid < 128) {
        s_src[tid] = nbrs[2 * (e0 + tid)];
        s_dst[tid] = nbrs[2 * (e0 + tid) + 1];
    }

    float acc[2][8][4];
    #pragma unroll
    for (int mi = 0; mi < 2; mi++)
        #pragma unroll
        for (int ni = 0; ni < 8; ni++)
            #pragma unroll
            for (int j = 0; j < 4; j++) acc[mi][ni][j] = 0.f;

    for (int kc = 0; kc < 4; kc++) {
        __syncthreads();
        // stage A chunk: gather + swish + split, [128 e][64 k]
        for (int idx = tid; idx < 128 * 16; idx += 256) {
            int e = idx >> 4, k = (idx & 15) * 4;
            float4 a = *(const float4*)&t[(size_t)s_src[e] * 256 + kc * 64 + k];
            float4 b = *(const float4*)&t[(size_t)s_dst[e] * 256 + kc * 64 + k];
            float x[4] = {swish(a.x + b.x), swish(a.y + b.y),
                          swish(a.z + b.z), swish(a.w + b.w)};
            #pragma unroll
            for (int j = 0; j < 4; j++) {
                __half hi, lo;
                split_h(x[j], hi, lo);
                Ah[e * HP + k + j] = hi;
                Al[e * HP + k + j] = lo;
            }
        }
        // stage B chunk: W[kc*64+kl][n] -> B[n][kl]
        for (int idx = tid; idx < 128 * 16; idx += 256) {
            int n = idx & 127, kl = (idx >> 7) * 4;
            #pragma unroll
            for (int j = 0; j < 4; j++) {
                float w = W[(size_t)(kc * 64 + kl + j) * 128 + n];
                __half hi, lo;
                split_h(w, hi, lo);
                Bh[n * HP + kl + j] = hi;
                Bl[n * HP + kl + j] = lo;
            }
        }
        __syncthreads();

        #pragma unroll
        for (int ks = 0; ks < 4; ks++) {
            int kl = ks * 16;
            unsigned ah[2][4], al[2][4];
            #pragma unroll
            for (int mi = 0; mi < 2; mi++) {
                int r = m0 + mi * 16;
                ah[mi][0] = *(const unsigned*)&Ah[(r + g) * HP + kl + 2 * tq];
                ah[mi][1] = *(const unsigned*)&Ah[(r + g + 8) * HP + kl + 2 * tq];
                ah[mi][2] = *(const unsigned*)&Ah[(r + g) * HP + kl + 8 + 2 * tq];
                ah[mi][3] = *(const unsigned*)&Ah[(r + g + 8) * HP + kl + 8 + 2 * tq];
                al[mi][0] = *(const unsigned*)&Al[(r + g) * HP + kl + 2 * tq];
                al[mi][1] = *(const unsigned*)&Al[(r + g + 8) * HP + kl + 2 * tq];
                al[mi][2] = *(const unsigned*)&Al[(r + g) * HP + kl + 8 + 2 * tq];
                al[mi][3] = *(const unsigned*)&Al[(r + g + 8) * HP + kl + 8 + 2 * tq];
            }
            #pragma unroll
            for (int ni = 0; ni < 8; ni++) {
                int n = n0w + ni * 8 + g;
                unsigned bh[2], bl[2];
                bh[0] = *(const unsigned*)&Bh[n * HP + kl + 2 * tq];
                bh[1] = *(const unsigned*)&Bh[n * HP + kl + 8 + 2 * tq];
                bl[0] = *(const unsigned*)&Bl[n * HP + kl + 2 * tq];
                bl[1] = *(const unsigned*)&Bl[n * HP + kl + 8 + 2 * tq];
                #pragma unroll
                for (int mi = 0; mi < 2; mi++) {
                    hmma(acc[mi][ni], ah[mi], bh);
                    hmma(acc[mi][ni], ah[mi], bl);
                    hmma(acc[mi][ni], al[mi], bh);
                }
            }
        }
    }

    // epilogue: eij += acc + bias
    #pragma unroll
    for (int mi = 0; mi < 2; mi++) {
        #pragma unroll
        for (int ni = 0; ni < 8; ni++) {
            int col = n0w + ni * 8 + 2 * tq;
            float2 bb = *(const float2*)&bias[col];
            size_t r0 = (size_t)(e0 + m0 + mi * 16 + g) * 128 + col;
            size_t r1 = (size_t)(e0 + m0 + mi * 16 + g + 8) * 128 + col;
            float2 o0 = *(const float2*)&eij[r0];
            float2 o1 = *(const float2*)&eij[r1];
            o0.x += bb.x + acc[mi][ni][0]; o0.y += bb.y + acc[mi][ni][1];
            o1.x += bb.x + acc[mi][ni][2]; o1.y += bb.y + acc[mi][ni][3];
            *(float2*)&eij[r0] = o0;
            *(float2*)&eij[r1] = o1;
        }
    }
}

// ================ HMMA fused readout ================
// hidden[128,256] = e_ij[128,128] @ ro_w1[128,256]; per-row sum of
// swish(h+b1)*w2 + b2 -> scalar; scatter forces.
constexpr int HP2 = 136;  // padded half stride for K=128 (272B rows)
__global__ void __launch_bounds__(256)
readout_mma(const float* __restrict__ W1, const float* __restrict__ b1,
            const float* __restrict__ w2, const float* __restrict__ b2,
            const int* __restrict__ nbrs, float* __restrict__ out) {
    extern __shared__ __align__(16) __half hsm[];
    __half* Ah = hsm;                 // [128][136]
    __half* Al = Ah + 128 * HP2;
    __half* Bh = Al + 128 * HP2;      // [128 n][136 k], per n-chunk
    __half* Bl = Bh + 128 * HP2;
    __shared__ float red[128][2];

    int tid = threadIdx.x;
    int wid = tid >> 5, lane = tid & 31;
    int g = lane >> 2, tq = lane & 3;
    int m0 = (wid & 3) * 32;
    int n0w = (wid >> 2) * 64;
    int nw = wid >> 2;
    int e0 = blockIdx.x * 128;

    // stage A once: e_ij rows, split
    for (int idx = tid; idx < 128 * 32; idx += 256) {
        int e = idx >> 5, k = (idx & 31) * 4;
        float4 a = *(const float4*)&g_eij[(size_t)(e0 + e) * 128 + k];
        float x[4] = {a.x, a.y, a.z, a.w};
        #pragma unroll
        for (int j = 0; j < 4; j++) {
            __half hi, lo;
            split_h(x[j], hi, lo);
            Ah[e * HP2 + k + j] = hi;
            Al[e * HP2 + k + j] = lo;
        }
    }

    float rs[2][2] = {{0.f, 0.f}, {0.f, 0.f}};  // [mi][g row / g+8 row]

    for (int nc = 0; nc < 2; nc++) {
        __syncthreads();
        // stage B: W1[k][nc*128 + n] -> B[n][k]
        for (int idx = tid; idx < 128 * 32; idx += 256) {
            int n = idx & 127, k = (idx >> 7) * 4;
            #pragma unroll
            for (int j = 0; j < 4; j++) {
                float w = W1[(size_t)(k + j) * 256 + nc * 128 + n];
                __half hi, lo;
                split_h(w, hi, lo);
                Bh[n * HP2 + k + j] = hi;
                Bl[n * HP2 + k + j] = lo;
            }
        }
        __syncthreads();

        float acc[2][8][4];
        #pragma unroll
        for (int mi = 0; mi < 2; mi++)
            #pragma unroll
            for (int ni = 0; ni < 8; ni++)
                #pragma unroll
                for (int j = 0; j < 4; j++) acc[mi][ni][j] = 0.f;

        #pragma unroll
        for (int ks = 0; ks < 8; ks++) {
            int kl = ks * 16;
            unsigned ah[2][4], al[2][4];
            #pragma unroll
            for (int mi = 0; mi < 2; mi++) {
                int r = m0 + mi * 16;
                ah[mi][0] = *(const unsigned*)&Ah[(r + g) * HP2 + kl + 2 * tq];
                ah[mi][1] = *(const unsigned*)&Ah[(r + g + 8) * HP2 + kl + 2 * tq];
                ah[mi][2] = *(const unsigned*)&Ah[(r + g) * HP2 + kl + 8 + 2 * tq];
                ah[mi][3] = *(const unsigned*)&Ah[(r + g + 8) * HP2 + kl + 8 + 2 * tq];
                al[mi][0] = *(const unsigned*)&Al[(r + g) * HP2 + kl + 2 * tq];
                al[mi][1] = *(const unsigned*)&Al[(r + g + 8) * HP2 + kl + 2 * tq];
                al[mi][2] = *(const unsigned*)&Al[(r + g) * HP2 + kl + 8 + 2 * tq];
                al[mi][3] = *(const unsigned*)&Al[(r + g + 8) * HP2 + kl + 8 + 2 * tq];
            }
            #pragma unroll
            for (int ni = 0; ni < 8; ni++) {
                int n = n0w + ni * 8 + g;
                unsigned bh[2], bl[2];
                bh[0] = *(const unsigned*)&Bh[n * HP2 + kl + 2 * tq];
                bh[1] = *(const unsigned*)&Bh[n * HP2 + kl + 8 + 2 * tq];
                bl[0] = *(const unsigned*)&Bl[n * HP2 + kl + 2 * tq];
                bl[1] = *(const unsigned*)&Bl[n * HP2 + kl + 8 + 2 * tq];
                #pragma unroll
                for (int mi = 0; mi < 2; mi++) {
                    hmma(acc[mi][ni], ah[mi], bh);
                    hmma(acc[mi][ni], ah[mi], bl);
                    hmma(acc[mi][ni], al[mi], bh);
                }
            }
        }

        // reduce this n-chunk into row sums
        #pragma unroll
        for (int mi = 0; mi < 2; mi++) {
            #pragma unroll
            for (int ni = 0; ni < 8; ni++) {
                int c = nc * 128 + n0w + ni * 8 + 2 * tq;
                float2 bb = *(const float2*)&b1[c];
                float2 ww = *(const float2*)&w2[c];
                rs[mi][0] += swish(acc[mi][ni][0] + bb.x) * ww.x
                           + swish(acc[mi][ni][1] + bb.y) * ww.y;
                rs[mi][1] += swish(acc[mi][ni][2] + bb.x) * ww.x
                           + swish(acc[mi][ni][3] + bb.y) * ww.y;
            }
        }
    }

    // cross-lane reduce over tq (quad)
    #pragma unroll
    for (int mi = 0; mi < 2; mi++) {
        #pragma unroll
        for (int h = 0; h < 2; h++) {
            float v = rs[mi][h];
            v += __shfl_xor_sync(0xffffffff, v, 1);
            v += __shfl_xor_sync(0xffffffff, v, 2);
            rs[mi][h] = v;
        }
    }
    if (tq == 0) {
        red[m0 + 0 * 16 + g][nw]     = rs[0][0];
        red[m0 + 0 * 16 + g + 8][nw] = rs[0][1];
        red[m0 + 1 * 16 + g][nw]     = rs[1][0];
        red[m0 + 1 * 16 + g + 8][nw] = rs[1][1];
    }
    __syncthreads();

    if (tid < 128) {
        int e = e0 + tid;
        float s = red[tid][0] + red[tid][1] + b2[0];
        int src = nbrs[2 * e], dst = nbrs[2 * e + 1];
        float fx = s * g_unit[(size_t)e * 3 + 0];
        float fy = s * g_unit[(size_t)e * 3 + 1];
        float fz = s * g_unit[(size_t)e * 3 + 2];
        atomicAdd(&out[src * 3 + 0], fx);
        atomicAdd(&out[src * 3 + 1], fy);
        atomicAdd(&out[src * 3 + 2], fz);
        atomicAdd(&out[dst * 3 + 0], -fx);
        atomicAdd(&out[dst * 3 + 1], -fy);
        atomicAdd(&out[dst * 3 + 2], -fz);
    }
}

// ---------------- host launcher ----------------
extern "C" void kernel_launch(void* const* d_in, const int* in_sizes, int n_in,
                              void* d_out, int out_size) {
    const float* xyz     = (const float*)d_in[0];
    const int*   z       = (const int*)  d_in[1];
    const int*   nbrs    = (const int*)  d_in[2];
    const float* emb     = (const float*)d_in[3];
    const float* de_w    = (const float*)d_in[4];
    const float* de_b    = (const float*)d_in[5];
    const float* msg_w1  = (const float*)d_in[6];
    const float* msg_b1  = (const float*)d_in[7];
    const float* msg_w2  = (const float*)d_in[8];
    const float* msg_b2  = (const float*)d_in[9];
    const float* msg_dw  = (const float*)d_in[10];
    const float* msg_db  = (const float*)d_in[11];
    const float* upd_u   = (const float*)d_in[12];
    const float* upd_v   = (const float*)d_in[13];
    const float* upd_w1  = (const float*)d_in[14];
    const float* upd_b1  = (const float*)d_in[15];
    const float* upd_w2  = (const float*)d_in[16];
    const float* upd_b2  = (const float*)d_in[17];
    const float* edge_w1 = (const float*)d_in[18];
    const float* edge_b1 = (const float*)d_in[19];
    const float* edge_w2 = (const float*)d_in[20];
    const float* edge_b2 = (const float*)d_in[21];
    const float* ro_w1   = (const float*)d_in[22];
    const float* ro_b1   = (const float*)d_in[23];
    const float* ro_w2   = (const float*)d_in[24];
    const float* ro_b2   = (const float*)d_in[25];
    float* out = (float*)d_out;

    float *p_rbf, *p_env, *p_eij, *p_s, *p_phi, *p_h1, *p_stk, *p_spl, *p_t;
    cudaGetSymbolAddress((void**)&p_rbf,  g_rbf);
    cudaGetSymbolAddress((void**)&p_env,  g_env);
    cudaGetSymbolAddress((void**)&p_eij,  g_eij);
    cudaGetSymbolAddress((void**)&p_s,    g_s);
    cudaGetSymbolAddress((void**)&p_phi,  g_phi);
    cudaGetSymbolAddress((void**)&p_h1,   g_h1);
    cudaGetSymbolAddress((void**)&p_stk,  g_stk);
    cudaGetSymbolAddress((void**)&p_spl,  g_spl);
    cudaGetSymbolAddress((void**)&p_t,    g_t);

    const int SMEM_E2 = 4 * 128 * HP * 2;    // 73728
    const int SMEM_RO = 4 * 128 * HP2 * 2;   // 139264
    cudaFuncSetAttribute(edge2_mma,  cudaFuncAttributeMaxDynamicSharedMemorySize, SMEM_E2);
    cudaFuncSetAttribute(readout_mma, cudaFuncAttributeMaxDynamicSharedMemorySize, SMEM_RO);
    cudaFuncSetAttribute(gemm_rt<256, true>,
                         cudaFuncAttributeMaxDynamicSharedMemorySize, 256 * GPAD * 4);

    const int smem128 = 128 * GPAD * 4;
    const int smem256 = 256 * GPAD * 4;
    const int gN = (NN + 63) / 64;   // 313
    const int gTC = EE / 128;        // 2500

    init_kernel<<<2048, 256>>>(emb, z, out);
    prep_kernel<<<(EE + 255) / 256, 256>>>(xyz, nbrs);

    // e_ij = (rbf @ de_w + de_b) * env
    mlp_gemm_small<RB, 128><<<(EE + 31) / 32, 128>>>(p_rbf, de_w, de_b, p_eij, p_env, EE);

    for (int l = 0; l < 3; l++) {
        int sel = l & 1;
        int cur = sel ^ 1;

        // phi = swish(s @ msg_w1 + b1) @ msg_w2 + b2
        gemm_rt<128, true><<<dim3(gN, 1), 256, smem128>>>(
            p_s, msg_w1 + l * 128 * 128, 128, msg_b1 + l * 128, 1.f, p_h1, NN);
        gemm_rt<128, false><<<dim3(gN, 3), 256, smem128>>>(
            p_h1, msg_w2 + l * 128 * 384, 384, msg_b2 + l * 384, 1.f, p_phi, NN);

        copy_v<<<(NN * 384 / 4 + 255) / 256, 256>>>(sel);
        msg_kernel<<<(EE + TE - 1) / TE, 128>>>(nbrs, msg_dw + l * RB * 384,
                                                msg_db + l * 384, sel);

        // update block
        upd1_kernel<<<(NN + TA - 1) / TA, 128>>>(upd_u + l * 128 * 128,
                                                 upd_v + l * 128 * 128, cur);
        gemm_rt<256, true><<<dim3(gN, 1), 256, smem256>>>(
            p_stk, upd_w1 + l * 256 * 128, 128, upd_b1 + l * 128, 1.f, p_h1, NN);
        gemm_rt<128, false><<<dim3(gN, 3), 256, smem128>>>(
            p_h1, upd_w2 + l * 128 * 384, 384, upd_b2 + l * 384, 1.f, p_spl, NN);
        apply_kernel<<<(NN * 128 + 255) / 256, 256>>>(cur);

        // edge MLP, factored: t = s @ edge_w1 + 0.5*b1 per NODE (FFMA);
        // e_ij += swish(t[src]+t[dst]) @ edge_w2 + b2 per EDGE (HMMA).
        gemm_rt<128, false><<<dim3(gN, 2), 256, smem128>>>(
            p_s, edge_w1 + l * 128 * 256, 256, edge_b1 + l * 256, 0.5f, p_t, NN);
        edge2_mma<<<gTC, 256, SMEM_E2>>>(p_t, edge_w2 + l * 256 * 128,
                                         edge_b2 + l * 128, nbrs, p_eij);
    }

    // fused HMMA readout
    readout_mma<<<gTC, 256, SMEM_RO>>>(ro_w1, ro_b1, ro_w2, ro_b2, nbrs, out);

    (void)in_sizes; (void)n_in; (void)out_size;
}

// round 5
// speedup vs baseline: 1.8639x; 1.1642x over previous
#include <cuda_runtime.h>
#include <cuda_fp16.h>
#include <math.h>

// ---------------- problem constants ----------------
constexpr int NN = 20000;
constexpr int EE = 320000;
constexpr int RB = 20;    // NRBF
constexpr float PI_F = 3.14159265358979323846f;
constexpr float EPS3 = 3e-15f;

// ---------------- device scratch ----------------
__device__ float g_rbf [(size_t)EE * RB];
__device__ float g_env [EE];
__device__ float g_unit[(size_t)EE * 3];
__device__ float g_eij [(size_t)EE * 128];
__device__ float g_s   [(size_t)NN * 128];
__device__ float g_v0  [(size_t)NN * 384];
__device__ float g_v1  [(size_t)NN * 384];
__device__ float g_phi [(size_t)NN * 384];
__device__ float g_h1  [(size_t)NN * 128];
__device__ float g_uv  [(size_t)NN * 384];
__device__ float g_dot [(size_t)NN * 128];
__device__ float g_stk [(size_t)NN * 256];
__device__ float g_spl [(size_t)NN * 384];
__device__ float g_t   [(size_t)NN * 256];
// CSR by src
__device__ int g_rowptr[NN + 1];
__device__ int g_cursor[NN];
__device__ int g_perm  [EE];

__device__ __forceinline__ float swish(float x) {
    return x / (1.f + expf(-x));
}

__device__ __forceinline__ void split_h(float x, __half& hi, __half& lo) {
    hi = __float2half_rn(x);
    lo = __float2half_rn(x - __half2float(hi));
}

__device__ __forceinline__ void hmma(float* d, const unsigned* a, const unsigned* b) {
    asm volatile(
        "mma.sync.aligned.m16n8k16.row.col.f32.f16.f16.f32 "
        "{%0,%1,%2,%3}, {%4,%5,%6,%7}, {%8,%9}, {%0,%1,%2,%3};"
        : "+f"(d[0]), "+f"(d[1]), "+f"(d[2]), "+f"(d[3])
        : "r"(a[0]), "r"(a[1]), "r"(a[2]), "r"(a[3]), "r"(b[0]), "r"(b[1]));
}

// ---------------- init ----------------
__global__ void init_kernel(const float* __restrict__ emb, const int* __restrict__ z,
                            float* __restrict__ out) {
    int stride = gridDim.x * blockDim.x;
    for (int i = blockIdx.x * blockDim.x + threadIdx.x; i < NN * 384; i += stride) {
        g_v0[i] = 0.f;
        if (i < NN * 128) {
            int n = i >> 7, f = i & 127;
            g_s[i] = emb[z[n] * 128 + f];
        }
        if (i < NN * 3) out[i] = 0.f;
    }
}

// ---------------- CSR build ----------------
__global__ void zero_rowptr() {
    int i = blockIdx.x * blockDim.x + threadIdx.x;
    if (i <= NN) g_rowptr[i] = 0;
}
__global__ void hist_kernel(const int* __restrict__ nbrs) {
    int e = blockIdx.x * blockDim.x + threadIdx.x;
    if (e < EE) atomicAdd(&g_rowptr[nbrs[2 * e] + 1], 1);
}
__global__ void scan_kernel() {
    __shared__ int sm[1024];
    __shared__ int carry;
    int t = threadIdx.x;
    if (t == 0) carry = 0;
    __syncthreads();
    int nch = (NN + 1 + 1023) / 1024;
    for (int c = 0; c < nch; c++) {
        int i = c * 1024 + t;
        int v = (i <= NN) ? g_rowptr[i] : 0;
        sm[t] = v;
        __syncthreads();
        #pragma unroll
        for (int off = 1; off < 1024; off <<= 1) {
            int x = (t >= off) ? sm[t - off] : 0;
            __syncthreads();
            sm[t] += x;
            __syncthreads();
        }
        if (i <= NN) g_rowptr[i] = sm[t] + carry;
        int total = sm[1023];
        __syncthreads();
        if (t == 0) carry += total;
        __syncthreads();
    }
}
__global__ void cursor_init() {
    int i = blockIdx.x * blockDim.x + threadIdx.x;
    if (i < NN) g_cursor[i] = g_rowptr[i];
}
__global__ void scatter_kernel(const int* __restrict__ nbrs) {
    int e = blockIdx.x * blockDim.x + threadIdx.x;
    if (e < EE) {
        int pos = atomicAdd(&g_cursor[nbrs[2 * e]], 1);
        g_perm[pos] = e;
    }
}

// ---------------- per-edge geometry ----------------
__global__ void prep_kernel(const float* __restrict__ xyz, const int* __restrict__ nbrs) {
    int e = blockIdx.x * blockDim.x + threadIdx.x;
    if (e >= EE) return;
    int s = nbrs[2 * e], d = nbrs[2 * e + 1];
    float dx = xyz[d * 3 + 0] - xyz[s * 3 + 0];
    float dy = xyz[d * 3 + 1] - xyz[s * 3 + 1];
    float dz = xyz[d * 3 + 2] - xyz[s * 3 + 2];
    float d2 = dx * dx + dy * dy + dz * dz + EPS3;
    float dist = sqrtf(d2);
    float inv = 1.f / dist;
    g_unit[(size_t)e * 3 + 0] = dx * inv;
    g_unit[(size_t)e * 3 + 1] = dy * inv;
    g_unit[(size_t)e * 3 + 2] = dz * inv;
    float env = (dist < 5.f) ? 0.5f * (cosf(dist * (PI_F / 5.f)) + 1.f) : 0.f;
    g_env[e] = env;
    float base = dist * (PI_F / 5.f);
    #pragma unroll
    for (int k = 1; k <= RB; k++) {
        g_rbf[(size_t)e * RB + (k - 1)] = sinf(base * (float)k) * inv;
    }
}

// ---------------- small-K GEMM (rbf K=20 init of e_ij) ----------------
template<int K, int NC>
__global__ void __launch_bounds__(NC)
mlp_gemm_small(const float* __restrict__ A, const float* __restrict__ W,
               const float* __restrict__ bias, float* __restrict__ C,
               const float* __restrict__ env, int M) {
    constexpr int TM = 32;
    constexpr int PAD = 36;
    __shared__ __align__(16) float As[K * PAD];
    int m0 = blockIdx.x * TM;
    int tid = threadIdx.x;
    for (int i = tid; i < TM * K; i += NC) {
        int r = i / K, c = i - r * K;
        int m = m0 + r;
        As[c * PAD + r] = (m < M) ? A[(size_t)m * K + c] : 0.f;
    }
    __syncthreads();
    float acc[TM];
    #pragma unroll
    for (int r = 0; r < TM; r++) acc[r] = 0.f;
    const float* Wj = W + tid;
    #pragma unroll
    for (int k = 0; k < K; k++) {
        float w = Wj[k * NC];
        const float4* row = reinterpret_cast<const float4*>(&As[k * PAD]);
        #pragma unroll
        for (int r4 = 0; r4 < TM / 4; r4++) {
            float4 a = row[r4];
            acc[r4 * 4 + 0] = fmaf(a.x, w, acc[r4 * 4 + 0]);
            acc[r4 * 4 + 1] = fmaf(a.y, w, acc[r4 * 4 + 1]);
            acc[r4 * 4 + 2] = fmaf(a.z, w, acc[r4 * 4 + 2]);
            acc[r4 * 4 + 3] = fmaf(a.w, w, acc[r4 * 4 + 3]);
        }
    }
    float bj = bias[tid];
    #pragma unroll
    for (int r = 0; r < TM; r++) {
        int m = m0 + r;
        if (m >= M) break;
        C[(size_t)m * NC + tid] = (acc[r] + bj) * env[m];
    }
}

// ================ generic HMMA GEMM ================
// C[:, col0:col0+128] (op)= A' @ W[:, col0:col0+128] + bias_scale*b
// A' row m: GATHER_SWISH ? swish(A[src[m]]+A[dst[m]]) : A[m]   (row stride = K)
// fp16 split emulation (AhBh + AhBl + AlBh), fp32 accumulators.
constexpr int HP = 72;  // padded half stride for 64-wide K chunk
template<int K, bool GATHER_SWISH, bool SWISH_OUT, bool ACCUM>
__global__ void __launch_bounds__(256)
hmma_gemm(const float* __restrict__ Ain, const float* __restrict__ W, int ldw,
          const float* __restrict__ bias, float bias_scale, float* __restrict__ C,
          const int* __restrict__ nbrs, int M) {
    extern __shared__ __align__(16) __half hsm[];
    __half* Ah = hsm;
    __half* Al = Ah + 128 * HP;
    __half* Bh = Al + 128 * HP;
    __half* Bl = Bh + 128 * HP;
    __shared__ int s_src[128], s_dst[128];

    int tid = threadIdx.x;
    int wid = tid >> 5, lane = tid & 31;
    int g = lane >> 2, tq = lane & 3;
    int wm0 = (wid & 3) * 32;
    int n0w = (wid >> 2) * 64;
    int m0b = blockIdx.x * 128;
    int col0 = blockIdx.y * 128;

    if (GATHER_SWISH && tid < 128) {
        int m = m0b + tid;
        s_src[tid] = (m < M) ? nbrs[2 * m] : 0;
        s_dst[tid] = (m < M) ? nbrs[2 * m + 1] : 0;
    }

    float acc[2][8][4];
    #pragma unroll
    for (int mi = 0; mi < 2; mi++)
        #pragma unroll
        for (int ni = 0; ni < 8; ni++)
            #pragma unroll
            for (int j = 0; j < 4; j++) acc[mi][ni][j] = 0.f;

    constexpr int NCH = K / 64;
    for (int kc = 0; kc < NCH; kc++) {
        __syncthreads();
        // stage A chunk [128 rows][64 k]
        for (int idx = tid; idx < 128 * 16; idx += 256) {
            int r = idx >> 4, k = (idx & 15) * 4;
            int m = m0b + r;
            float x[4] = {0.f, 0.f, 0.f, 0.f};
            if (m < M) {
                if (GATHER_SWISH) {
                    float4 a = *(const float4*)&Ain[(size_t)s_src[r] * K + kc * 64 + k];
                    float4 b = *(const float4*)&Ain[(size_t)s_dst[r] * K + kc * 64 + k];
                    x[0] = swish(a.x + b.x); x[1] = swish(a.y + b.y);
                    x[2] = swish(a.z + b.z); x[3] = swish(a.w + b.w);
                } else {
                    float4 a = *(const float4*)&Ain[(size_t)m * K + kc * 64 + k];
                    x[0] = a.x; x[1] = a.y; x[2] = a.z; x[3] = a.w;
                }
            }
            #pragma unroll
            for (int j = 0; j < 4; j++) {
                __half hi, lo;
                split_h(x[j], hi, lo);
                Ah[r * HP + k + j] = hi;
                Al[r * HP + k + j] = lo;
            }
        }
        // stage B chunk: W[kc*64+kl][col0+n] -> B[n][kl]
        for (int idx = tid; idx < 128 * 16; idx += 256) {
            int n = idx & 127, kl = (idx >> 7) * 4;
            #pragma unroll
            for (int j = 0; j < 4; j++) {
                float w = W[(size_t)(kc * 64 + kl + j) * ldw + col0 + n];
                __half hi, lo;
                split_h(w, hi, lo);
                Bh[n * HP + kl + j] = hi;
                Bl[n * HP + kl + j] = lo;
            }
        }
        __syncthreads();

        #pragma unroll
        for (int ks = 0; ks < 4; ks++) {
            int kl = ks * 16;
            unsigned ah[2][4], al[2][4];
            #pragma unroll
            for (int mi = 0; mi < 2; mi++) {
                int r = wm0 + mi * 16;
                ah[mi][0] = *(const unsigned*)&Ah[(r + g) * HP + kl + 2 * tq];
                ah[mi][1] = *(const unsigned*)&Ah[(r + g + 8) * HP + kl + 2 * tq];
                ah[mi][2] = *(const unsigned*)&Ah[(r + g) * HP + kl + 8 + 2 * tq];
                ah[mi][3] = *(const unsigned*)&Ah[(r + g + 8) * HP + kl + 8 + 2 * tq];
                al[mi][0] = *(const unsigned*)&Al[(r + g) * HP + kl + 2 * tq];
                al[mi][1] = *(const unsigned*)&Al[(r + g + 8) * HP + kl + 2 * tq];
                al[mi][2] = *(const unsigned*)&Al[(r + g) * HP + kl + 8 + 2 * tq];
                al[mi][3] = *(const unsigned*)&Al[(r + g + 8) * HP + kl + 8 + 2 * tq];
            }
            #pragma unroll
            for (int ni = 0; ni < 8; ni++) {
                int n = n0w + ni * 8 + g;
                unsigned bh[2], bl[2];
                bh[0] = *(const unsigned*)&Bh[n * HP + kl + 2 * tq];
                bh[1] = *(const unsigned*)&Bh[n * HP + kl + 8 + 2 * tq];
                bl[0] = *(const unsigned*)&Bl[n * HP + kl + 2 * tq];
                bl[1] = *(const unsigned*)&Bl[n * HP + kl + 8 + 2 * tq];
                #pragma unroll
                for (int mi = 0; mi < 2; mi++) {
                    hmma(acc[mi][ni], ah[mi], bh);
                    hmma(acc[mi][ni], ah[mi], bl);
                    hmma(acc[mi][ni], al[mi], bh);
                }
            }
        }
    }

    // epilogue
    #pragma unroll
    for (int mi = 0; mi < 2; mi++) {
        #pragma unroll
        for (int ni = 0; ni < 8; ni++) {
            int col = n0w + ni * 8 + 2 * tq;
            float2 bb = *(const float2*)&bias[col0 + col];
            bb.x *= bias_scale; bb.y *= bias_scale;
            #pragma unroll
            for (int h = 0; h < 2; h++) {
                int m = m0b + wm0 + mi * 16 + g + h * 8;
                if (m >= M) continue;
                float2 o;
                o.x = acc[mi][ni][2 * h + 0] + bb.x;
                o.y = acc[mi][ni][2 * h + 1] + bb.y;
                if (SWISH_OUT) { o.x = swish(o.x); o.y = swish(o.y); }
                float* cp = &C[(size_t)m * ldw + col0 + col];
                if (ACCUM) {
                    float2 old = *(const float2*)cp;
                    o.x += old.x; o.y += old.y;
                }
                *(float2*)cp = o;
            }
        }
    }
}

// ---------------- CSR message pass: no atomics, fuses copy_v ----------------
__global__ void __launch_bounds__(128)
msg2_kernel(const int* __restrict__ nbrs, const float* __restrict__ dw,
            const float* __restrict__ db, int sel) {
    int n = blockIdx.x;
    int t = threadIdx.x;

    float dwr0[RB], dwr1[RB], dwr2[RB];
    #pragma unroll
    for (int k = 0; k < RB; k++) {
        dwr0[k] = dw[k * 384 + t];
        dwr1[k] = dw[k * 384 + t + 128];
        dwr2[k] = dw[k * 384 + t + 256];
    }
    float db0 = db[t], db1 = db[t + 128], db2 = db[t + 256];

    const float* vold = sel ? g_v1 : g_v0;
    float*       vnew = sel ? g_v0 : g_v1;

    int start = g_rowptr[n], end = g_rowptr[n + 1];
    float accs = 0.f, av0 = 0.f, av1 = 0.f, av2 = 0.f;

    for (int i = start; i < end; i++) {
        int e = g_perm[i];
        int dst = nbrs[2 * e + 1];
        float env = g_env[e];
        const float4* rb4 = (const float4*)&g_rbf[(size_t)e * RB];
        float4 r0 = rb4[0], r1 = rb4[1], r2 = rb4[2], r3 = rb4[3], r4 = rb4[4];
        float rb[RB] = {r0.x, r0.y, r0.z, r0.w, r1.x, r1.y, r1.z, r1.w,
                        r2.x, r2.y, r2.z, r2.w, r3.x, r3.y, r3.z, r3.w,
                        r4.x, r4.y, r4.z, r4.w};
        float a0 = db0, a1 = db1, a2 = db2;
        #pragma unroll
        for (int k = 0; k < RB; k++) {
            a0 = fmaf(rb[k], dwr0[k], a0);
            a1 = fmaf(rb[k], dwr1[k], a1);
            a2 = fmaf(rb[k], dwr2[k], a2);
        }
        a0 *= env; a1 *= env; a2 *= env;

        const float* ph = g_phi + (size_t)dst * 384;
        float s0 = ph[t] * a0;
        float s1 = ph[t + 128] * a1;
        float s2 = ph[t + 256] * a2;
        accs += s1;

        float ux = g_unit[(size_t)e * 3 + 0];
        float uy = g_unit[(size_t)e * 3 + 1];
        float uz = g_unit[(size_t)e * 3 + 2];
        const float* vo = vold + (size_t)dst * 384 + 3 * t;
        av0 += fmaf(s0, vo[0], s2 * ux);
        av1 += fmaf(s0, vo[1], s2 * uy);
        av2 += fmaf(s0, vo[2], s2 * uz);
    }

    g_s[(size_t)n * 128 + t] += accs;
    const float* vs = vold + (size_t)n * 384 + 3 * t;
    float*       vp = vnew + (size_t)n * 384 + 3 * t;
    vp[0] = vs[0] + av0;
    vp[1] = vs[1] + av1;
    vp[2] = vs[2] + av2;
}

// ---------------- update stage 1 ----------------
constexpr int TA = 8;
__global__ void __launch_bounds__(128)
upd1_kernel(const float* __restrict__ U, const float* __restrict__ Vw, int sel) {
    __shared__ __align__(16) float v_s[TA * 384];
    int t = threadIdx.x;
    int n0 = blockIdx.x * TA;
    const float* vcur = sel ? g_v1 : g_v0;

    for (int i = t; i < TA * 384; i += 128) {
        size_t gi = (size_t)n0 * 384 + i;
        v_s[i] = (gi < (size_t)NN * 384) ? vcur[gi] : 0.f;
    }
    __syncthreads();

    float uv[TA][3], vv[TA][3];
    #pragma unroll
    for (int a = 0; a < TA; a++)
        #pragma unroll
        for (int d = 0; d < 3; d++) { uv[a][d] = 0.f; vv[a][d] = 0.f; }

    for (int f4 = 0; f4 < 32; f4++) {
        float u0 = U[(f4 * 4 + 0) * 128 + t];
        float u1 = U[(f4 * 4 + 1) * 128 + t];
        float u2 = U[(f4 * 4 + 2) * 128 + t];
        float u3 = U[(f4 * 4 + 3) * 128 + t];
        float w0 = Vw[(f4 * 4 + 0) * 128 + t];
        float w1 = Vw[(f4 * 4 + 1) * 128 + t];
        float w2 = Vw[(f4 * 4 + 2) * 128 + t];
        float w3 = Vw[(f4 * 4 + 3) * 128 + t];
        #pragma unroll
        for (int a = 0; a < TA; a++) {
            const float4* vp = reinterpret_cast<const float4*>(&v_s[a * 384 + f4 * 12]);
            float4 p0 = vp[0], p1 = vp[1], p2 = vp[2];
            uv[a][0] = fmaf(p0.x, u0, fmaf(p0.w, u1, fmaf(p1.z, u2, fmaf(p2.y, u3, uv[a][0]))));
            uv[a][1] = fmaf(p0.y, u0, fmaf(p1.x, u1, fmaf(p1.w, u2, fmaf(p2.z, u3, uv[a][1]))));
            uv[a][2] = fmaf(p0.z, u0, fmaf(p1.y, u1, fmaf(p2.x, u2, fmaf(p2.w, u3, uv[a][2]))));
            vv[a][0] = fmaf(p0.x, w0, fmaf(p0.w, w1, fmaf(p1.z, w2, fmaf(p2.y, w3, vv[a][0]))));
            vv[a][1] = fmaf(p0.y, w0, fmaf(p1.x, w1, fmaf(p1.w, w2, fmaf(p2.z, w3, vv[a][1]))));
            vv[a][2] = fmaf(p0.z, w0, fmaf(p1.y, w1, fmaf(p2.x, w2, fmaf(p2.w, w3, vv[a][2]))));
        }
    }

    #pragma unroll
    for (int a = 0; a < TA; a++) {
        int n = n0 + a;
        if (n >= NN) break;
        float dt = uv[a][0] * vv[a][0] + uv[a][1] * vv[a][1] + uv[a][2] * vv[a][2];
        float vn = sqrtf(vv[a][0] * vv[a][0] + vv[a][1] * vv[a][1] + vv[a][2] * vv[a][2] + EPS3);
        g_uv[(size_t)n * 384 + 3 * t + 0] = uv[a][0];
        g_uv[(size_t)n * 384 + 3 * t + 1] = uv[a][1];
        g_uv[(size_t)n * 384 + 3 * t + 2] = uv[a][2];
        g_dot[(size_t)n * 128 + t] = dt;
        g_stk[(size_t)n * 256 + t] = g_s[(size_t)n * 128 + t];
        g_stk[(size_t)n * 256 + 128 + t] = vn;
    }
}

// ---------------- update apply ----------------
__global__ void apply_kernel(int sel) {
    int i = blockIdx.x * blockDim.x + threadIdx.x;
    if (i >= NN * 128) return;
    int n = i >> 7, g = i & 127;
    float avv = g_spl[(size_t)n * 384 + g];
    float asv = g_spl[(size_t)n * 384 + 128 + g];
    float ass = g_spl[(size_t)n * 384 + 256 + g];
    float* v = (sel ? g_v1 : g_v0) + (size_t)n * 384 + 3 * g;
    const float* uv = g_uv + (size_t)n * 384 + 3 * g;
    v[0] += uv[0] * avv;
    v[1] += uv[1] * avv;
    v[2] += uv[2] * avv;
    g_s[i] += g_dot[i] * asv + ass;
}

// ================ HMMA fused readout ================
constexpr int HP2 = 136;
__global__ void __launch_bounds__(256)
readout_mma(const float* __restrict__ W1, const float* __restrict__ b1,
            const float* __restrict__ w2, const float* __restrict__ b2,
            const int* __restrict__ nbrs, float* __restrict__ out) {
    extern __shared__ __align__(16) __half hsm[];
    __half* Ah = hsm;
    __half* Al = Ah + 128 * HP2;
    __half* Bh = Al + 128 * HP2;
    __half* Bl = Bh + 128 * HP2;
    __shared__ float red[128][2];

    int tid = threadIdx.x;
    int wid = tid >> 5, lane = tid & 31;
    int g = lane >> 2, tq = lane & 3;
    int m0 = (wid & 3) * 32;
    int n0w = (wid >> 2) * 64;
    int nw = wid >> 2;
    int e0 = blockIdx.x * 128;

    for (int idx = tid; idx < 128 * 32; idx += 256) {
        int e = idx >> 5, k = (idx & 31) * 4;
        float4 a = *(const float4*)&g_eij[(size_t)(e0 + e) * 128 + k];
        float x[4] = {a.x, a.y, a.z, a.w};
        #pragma unroll
        for (int j = 0; j < 4; j++) {
            __half hi, lo;
            split_h(x[j], hi, lo);
            Ah[e * HP2 + k + j] = hi;
            Al[e * HP2 + k + j] = lo;
        }
    }

    float rs[2][2] = {{0.f, 0.f}, {0.f, 0.f}};

    for (int nc = 0; nc < 2; nc++) {
        __syncthreads();
        for (int idx = tid; idx < 128 * 32; idx += 256) {
            int n = idx & 127, k = (idx >> 7) * 4;
            #pragma unroll
            for (int j = 0; j < 4; j++) {
                float w = W1[(size_t)(k + j) * 256 + nc * 128 + n];
                __half hi, lo;
                split_h(w, hi, lo);
                Bh[n * HP2 + k + j] = hi;
                Bl[n * HP2 + k + j] = lo;
            }
        }
        __syncthreads();

        float acc[2][8][4];
        #pragma unroll
        for (int mi = 0; mi < 2; mi++)
            #pragma unroll
            for (int ni = 0; ni < 8; ni++)
                #pragma unroll
                for (int j = 0; j < 4; j++) acc[mi][ni][j] = 0.f;

        #pragma unroll
        for (int ks = 0; ks < 8; ks++) {
            int kl = ks * 16;
            unsigned ah[2][4], al[2][4];
            #pragma unroll
            for (int mi = 0; mi < 2; mi++) {
                int r = m0 + mi * 16;
                ah[mi][0] = *(const unsigned*)&Ah[(r + g) * HP2 + kl + 2 * tq];
                ah[mi][1] = *(const unsigned*)&Ah[(r + g + 8) * HP2 + kl + 2 * tq];
                ah[mi][2] = *(const unsigned*)&Ah[(r + g) * HP2 + kl + 8 + 2 * tq];
                ah[mi][3] = *(const unsigned*)&Ah[(r + g + 8) * HP2 + kl + 8 + 2 * tq];
                al[mi][0] = *(const unsigned*)&Al[(r + g) * HP2 + kl + 2 * tq];
                al[mi][1] = *(const unsigned*)&Al[(r + g + 8) * HP2 + kl + 2 * tq];
                al[mi][2] = *(const unsigned*)&Al[(r + g) * HP2 + kl + 8 + 2 * tq];
                al[mi][3] = *(const unsigned*)&Al[(r + g + 8) * HP2 + kl + 8 + 2 * tq];
            }
            #pragma unroll
            for (int ni = 0; ni < 8; ni++) {
                int n = n0w + ni * 8 + g;
                unsigned bh[2], bl[2];
                bh[0] = *(const unsigned*)&Bh[n * HP2 + kl + 2 * tq];
                bh[1] = *(const unsigned*)&Bh[n * HP2 + kl + 8 + 2 * tq];
                bl[0] = *(const unsigned*)&Bl[n * HP2 + kl + 2 * tq];
                bl[1] = *(const unsigned*)&Bl[n * HP2 + kl + 8 + 2 * tq];
                #pragma unroll
                for (int mi = 0; mi < 2; mi++) {
                    hmma(acc[mi][ni], ah[mi], bh);
                    hmma(acc[mi][ni], ah[mi], bl);
                    hmma(acc[mi][ni], al[mi], bh);
                }
            }
        }

        #pragma unroll
        for (int mi = 0; mi < 2; mi++) {
            #pragma unroll
            for (int ni = 0; ni < 8; ni++) {
                int c = nc * 128 + n0w + ni * 8 + 2 * tq;
                float2 bb = *(const float2*)&b1[c];
                float2 ww = *(const float2*)&w2[c];
                rs[mi][0] += swish(acc[mi][ni][0] + bb.x) * ww.x
                           + swish(acc[mi][ni][1] + bb.y) * ww.y;
                rs[mi][1] += swish(acc[mi][ni][2] + bb.x) * ww.x
                           + swish(acc[mi][ni][3] + bb.y) * ww.y;
            }
        }
    }

    #pragma unroll
    for (int mi = 0; mi < 2; mi++) {
        #pragma unroll
        for (int h = 0; h < 2; h++) {
            float v = rs[mi][h];
            v += __shfl_xor_sync(0xffffffff, v, 1);
            v += __shfl_xor_sync(0xffffffff, v, 2);
            rs[mi][h] = v;
        }
    }
    if (tq == 0) {
        red[m0 + g][nw]          = rs[0][0];
        red[m0 + g + 8][nw]      = rs[0][1];
        red[m0 + 16 + g][nw]     = rs[1][0];
        red[m0 + 16 + g + 8][nw] = rs[1][1];
    }
    __syncthreads();

    if (tid < 128) {
        int e = e0 + tid;
        float s = red[tid][0] + red[tid][1] + b2[0];
        int src = nbrs[2 * e], dst = nbrs[2 * e + 1];
        float fx = s * g_unit[(size_t)e * 3 + 0];
        float fy = s * g_unit[(size_t)e * 3 + 1];
        float fz = s * g_unit[(size_t)e * 3 + 2];
        atomicAdd(&out[src * 3 + 0], fx);
        atomicAdd(&out[src * 3 + 1], fy);
        atomicAdd(&out[src * 3 + 2], fz);
        atomicAdd(&out[dst * 3 + 0], -fx);
        atomicAdd(&out[dst * 3 + 1], -fy);
        atomicAdd(&out[dst * 3 + 2], -fz);
    }
}

// ---------------- host launcher ----------------
extern "C" void kernel_launch(void* const* d_in, const int* in_sizes, int n_in,
                              void* d_out, int out_size) {
    const float* xyz     = (const float*)d_in[0];
    const int*   z       = (const int*)  d_in[1];
    const int*   nbrs    = (const int*)  d_in[2];
    const float* emb     = (const float*)d_in[3];
    const float* de_w    = (const float*)d_in[4];
    const float* de_b    = (const float*)d_in[5];
    const float* msg_w1  = (const float*)d_in[6];
    const float* msg_b1  = (const float*)d_in[7];
    const float* msg_w2  = (const float*)d_in[8];
    const float* msg_b2  = (const float*)d_in[9];
    const float* msg_dw  = (const float*)d_in[10];
    const float* msg_db  = (const float*)d_in[11];
    const float* upd_u   = (const float*)d_in[12];
    const float* upd_v   = (const float*)d_in[13];
    const float* upd_w1  = (const float*)d_in[14];
    const float* upd_b1  = (const float*)d_in[15];
    const float* upd_w2  = (const float*)d_in[16];
    const float* upd_b2  = (const float*)d_in[17];
    const float* edge_w1 = (const float*)d_in[18];
    const float* edge_b1 = (const float*)d_in[19];
    const float* edge_w2 = (const float*)d_in[20];
    const float* edge_b2 = (const float*)d_in[21];
    const float* ro_w1   = (const float*)d_in[22];
    const float* ro_b1   = (const float*)d_in[23];
    const float* ro_w2   = (const float*)d_in[24];
    const float* ro_b2   = (const float*)d_in[25];
    float* out = (float*)d_out;

    float *p_rbf, *p_env, *p_eij, *p_s, *p_phi, *p_h1, *p_stk, *p_spl, *p_t;
    cudaGetSymbolAddress((void**)&p_rbf,  g_rbf);
    cudaGetSymbolAddress((void**)&p_env,  g_env);
    cudaGetSymbolAddress((void**)&p_eij,  g_eij);
    cudaGetSymbolAddress((void**)&p_s,    g_s);
    cudaGetSymbolAddress((void**)&p_phi,  g_phi);
    cudaGetSymbolAddress((void**)&p_h1,   g_h1);
    cudaGetSymbolAddress((void**)&p_stk,  g_stk);
    cudaGetSymbolAddress((void**)&p_spl,  g_spl);
    cudaGetSymbolAddress((void**)&p_t,    g_t);

    const int SMEM_HM = 4 * 128 * HP * 2;    // 73728
    const int SMEM_RO = 4 * 128 * HP2 * 2;   // 139264
    cudaFuncSetAttribute(hmma_gemm<128, false, true,  false>,
                         cudaFuncAttributeMaxDynamicSharedMemorySize, SMEM_HM);
    cudaFuncSetAttribute(hmma_gemm<128, false, false, false>,
                         cudaFuncAttributeMaxDynamicSharedMemorySize, SMEM_HM);
    cudaFuncSetAttribute(hmma_gemm<256, false, true,  false>,
                         cudaFuncAttributeMaxDynamicSharedMemorySize, SMEM_HM);
    cudaFuncSetAttribute(hmma_gemm<256, true,  false, true>,
                         cudaFuncAttributeMaxDynamicSharedMemorySize, SMEM_HM);
    cudaFuncSetAttribute(readout_mma,
                         cudaFuncAttributeMaxDynamicSharedMemorySize, SMEM_RO);

    const int gH = (NN + 127) / 128;  // 157
    const int gE = EE / 128;          // 2500

    init_kernel<<<2048, 256>>>(emb, z, out);
    prep_kernel<<<(EE + 255) / 256, 256>>>(xyz, nbrs);

    // CSR build (per call; nbrs fixed within a call)
    zero_rowptr<<<(NN + 256) / 256, 256>>>();
    hist_kernel<<<(EE + 255) / 256, 256>>>(nbrs);
    scan_kernel<<<1, 1024>>>();
    cursor_init<<<(NN + 255) / 256, 256>>>();
    scatter_kernel<<<(EE + 255) / 256, 256>>>(nbrs);

    // e_ij = (rbf @ de_w + de_b) * env
    mlp_gemm_small<RB, 128><<<(EE + 31) / 32, 128>>>(p_rbf, de_w, de_b, p_eij, p_env, EE);

    for (int l = 0; l < 3; l++) {
        int sel = l & 1;
        int cur = sel ^ 1;

        // phi = swish(s @ msg_w1 + b1) @ msg_w2 + b2
        hmma_gemm<128, false, true, false><<<dim3(gH, 1), 256, SMEM_HM>>>(
            p_s, msg_w1 + l * 128 * 128, 128, msg_b1 + l * 128, 1.f, p_h1, nullptr, NN);
        hmma_gemm<128, false, false, false><<<dim3(gH, 3), 256, SMEM_HM>>>(
            p_h1, msg_w2 + l * 128 * 384, 384, msg_b2 + l * 384, 1.f, p_phi, nullptr, NN);

        // CSR message pass (atomic-free, fuses copy_v)
        msg2_kernel<<<NN, 128>>>(nbrs, msg_dw + l * RB * 384, msg_db + l * 384, sel);

        // update block
        upd1_kernel<<<(NN + TA - 1) / TA, 128>>>(upd_u + l * 128 * 128,
                                                 upd_v + l * 128 * 128, cur);
        hmma_gemm<256, false, true, false><<<dim3(gH, 1), 256, SMEM_HM>>>(
            p_stk, upd_w1 + l * 256 * 128, 128, upd_b1 + l * 128, 1.f, p_h1, nullptr, NN);
        hmma_gemm<128, false, false, false><<<dim3(gH, 3), 256, SMEM_HM>>>(
            p_h1, upd_w2 + l * 128 * 384, 384, upd_b2 + l * 384, 1.f, p_spl, nullptr, NN);
        apply_kernel<<<(NN * 128 + 255) / 256, 256>>>(cur);

        // edge MLP, factored: t = s @ edge_w1 + 0.5*b1 per NODE;
        // e_ij += swish(t[src]+t[dst]) @ edge_w2 + b2 per EDGE.
        hmma_gemm<128, false, false, false><<<dim3(gH, 2), 256, SMEM_HM>>>(
            p_s, edge_w1 + l * 128 * 256, 256, edge_b1 + l * 256, 0.5f, p_t, nullptr, NN);
        hmma_gemm<256, true, false, true><<<dim3(gE, 1), 256, SMEM_HM>>>(
            p_t, edge_w2 + l * 256 * 128, 128, edge_b2 + l * 128, 1.f, p_eij, nbrs, EE);
    }

    // fused HMMA readout
    readout_mma<<<gE, 256, SMEM_RO>>>(ro_w1, ro_b1, ro_w2, ro_b2, nbrs, out);

    (void)in_sizes; (void)n_in; (void)out_size;
}